// round 12
// baseline (speedup 1.0000x reference)
#include <cuda_runtime.h>
#include <cuda_bf16.h>
#include <cstdint>

#define NN 100000
#define EE 800000
#define DD 64
#define HH 4
#define HC 256

#define GEMM_BLKS 782     // ceil(NN/128)
#define HALF_BLKS 391
#define HALF_ROWS (HALF_BLKS * 128)   // 50048

// ---- scratch (static device globals: allocation-free) ----
__device__ float g_q[(size_t)NN * HC];                 // fp32 Q  [N][256]
__device__ __nv_bfloat16 g_kv[(size_t)NN * 512];       // bf16 K||V per node: [N][512]
__device__ float g_skip[(size_t)NN * DD];
__device__ float g_h[(size_t)NN * DD];
__device__ int   g_cnt[NN];
__device__ int   g_indptr[NN + 1];
__device__ int   g_cursor[NN];
__device__ int   g_col[EE];
__device__ int   g_bsum[512];
__device__ int   g_boff[512];
// W in bf16 hi/lo, transposed: [layer][chunk 13][part 2][n 64][k 64]
__device__ __nv_bfloat16 g_wb[2 * 13 * 2 * 64 * 64];

__device__ __forceinline__ uint32_t smem_u32(const void* p) {
    uint32_t a;
    asm("{ .reg .u64 t; cvta.to.shared.u64 t, %1; cvt.u32.u64 %0, t; }" : "=r"(a) : "l"(p));
    return a;
}

#define LDMX4(d0, d1, d2, d3, a) \
    asm volatile("ldmatrix.sync.aligned.m8n8.x4.shared.b16 {%0,%1,%2,%3}, [%4];" \
                 : "=r"(d0), "=r"(d1), "=r"(d2), "=r"(d3) : "r"(a))

#define MMA16816(c, a, b0, b1) \
    asm volatile("mma.sync.aligned.m16n8k16.row.col.f32.bf16.bf16.f32 " \
                 "{%0,%1,%2,%3}, {%4,%5,%6,%7}, {%8,%9}, {%0,%1,%2,%3};" \
                 : "+f"((c)[0]), "+f"((c)[1]), "+f"((c)[2]), "+f"((c)[3]) \
                 : "r"((a)[0]), "r"((a)[1]), "r"((a)[2]), "r"((a)[3]), "r"(b0), "r"(b1))

// ================= CSR build (per call, deterministic input) =================
__global__ void zero_cnt_kernel() {
    int i = blockIdx.x * blockDim.x + threadIdx.x;
    if (i < NN) g_cnt[i] = 0;
}
__global__ void hist_kernel(const int* __restrict__ ei) {
    int e = blockIdx.x * blockDim.x + threadIdx.x;
    if (e < EE) atomicAdd(&g_cnt[ei[EE + e]], 1);
}

// ---- hierarchical scan: k1 local block scans, k2 block-sum scan, k3 offset add ----
__global__ void __launch_bounds__(256) scan_local() {
    __shared__ int s_w[8];
    int tid = threadIdx.x, lane = tid & 31, wid = tid >> 5;
    int i = blockIdx.x * 256 + tid;
    int v = (i < NN) ? g_cnt[i] : 0;
    int x = v;
#pragma unroll
    for (int d = 1; d < 32; d <<= 1) {
        int t = __shfl_up_sync(0xffffffffu, x, d);
        if (lane >= d) x += t;
    }
    if (lane == 31) s_w[wid] = x;
    __syncthreads();
    if (wid == 0 && lane < 8) {
        int y = s_w[lane];
#pragma unroll
        for (int d = 1; d < 8; d <<= 1) {
            int t = __shfl_up_sync(0xffu, y, d);
            if (lane >= d) y += t;
        }
        s_w[lane] = y;
    }
    __syncthreads();
    int excl = (wid > 0 ? s_w[wid - 1] : 0) + x - v;
    if (i < NN) g_indptr[i] = excl;            // local exclusive (offset added in k3)
    if (tid == 255) g_bsum[blockIdx.x] = s_w[7];
}

__global__ void __launch_bounds__(512) scan_bsums(int nblocks) {
    __shared__ int s_w[16];
    int tid = threadIdx.x, lane = tid & 31, wid = tid >> 5;
    int v = (tid < nblocks) ? g_bsum[tid] : 0;
    int x = v;
#pragma unroll
    for (int d = 1; d < 32; d <<= 1) {
        int t = __shfl_up_sync(0xffffffffu, x, d);
        if (lane >= d) x += t;
    }
    if (lane == 31) s_w[wid] = x;
    __syncthreads();
    if (wid == 0 && lane < 16) {
        int y = s_w[lane];
#pragma unroll
        for (int d = 1; d < 16; d <<= 1) {
            int t = __shfl_up_sync(0xffffu, y, d);
            if (lane >= d) y += t;
        }
        s_w[lane] = y;
    }
    __syncthreads();
    int excl = (wid > 0 ? s_w[wid - 1] : 0) + x - v;
    if (tid < nblocks) g_boff[tid] = excl;
}

__global__ void __launch_bounds__(256) scan_add() {
    int i = blockIdx.x * 256 + threadIdx.x;
    if (i < NN) {
        int val = g_indptr[i] + g_boff[blockIdx.x];
        g_indptr[i] = val;
        g_cursor[i] = val;
    }
    if (i == 0) g_indptr[NN] = EE;   // total edge count is constant
}

__global__ void scatter_kernel(const int* __restrict__ ei) {
    int e = blockIdx.x * blockDim.x + threadIdx.x;
    if (e < EE) {
        int d = ei[EE + e];
        int pos = atomicAdd(&g_cursor[d], 1);
        g_col[pos] = ei[e];
    }
}

// ============ W prep (one layer): transpose + bf16 hi/lo split ============
__global__ void prep_w(const float* __restrict__ Wq, const float* __restrict__ Wk,
                       const float* __restrict__ Wv, const float* __restrict__ Ws,
                       __nv_bfloat16* __restrict__ dst) {
    int c = blockIdx.x;           // 0..12
    for (int i = threadIdx.x; i < 4096; i += 256) {
        int n = i >> 6, k = i & 63;
        float w;
        if (c < 4)       w = Wq[k * 256 + c * 64 + n];
        else if (c < 8)  w = Wk[k * 256 + (c - 4) * 64 + n];
        else if (c < 12) w = Wv[k * 256 + (c - 8) * 64 + n];
        else             w = Ws[k * 64 + n];
        __nv_bfloat16 hi = __float2bfloat16(w);
        float lo = w - __bfloat162float(hi);
        dst[c * 8192 + i]        = hi;
        dst[c * 8192 + 4096 + i] = __float2bfloat16(lo);
    }
}

// ============ mma.sync GEMM: 128 rows x 832 cols, bf16x3 split ============
#define SM_BIAS 0                    // 832 floats = 3328
#define SM_AHI  3584                 // 128 x 72 bf16 = 18432
#define SM_ALO  22016                // 18432
#define SM_BHI  40448                // 64 x 72 bf16 = 9216
#define SM_BLO  49664                // 9216
#define SM_STG  58880                // 128 x 68 fp32 = 34816
#define SM_TOT  93696
#define LDA 72
#define LDB 72
#define STG 68

__global__ void __launch_bounds__(128) tc_gemm(
    const float* __restrict__ Xext, int useGh,
    const float* __restrict__ bq, const float* __restrict__ bk,
    const float* __restrict__ bv, const float* __restrict__ bs,
    const __nv_bfloat16* __restrict__ wb, int nrows, int row_base)
{
    extern __shared__ char smem[];
    uint32_t sb = smem_u32(smem);
    const float* X = useGh ? g_h : Xext;
    int tid = threadIdx.x, w = tid >> 5, l = tid & 31;
    int row0 = (row_base + blockIdx.x) * 128;
    float* biasSm = reinterpret_cast<float*>(smem + SM_BIAS);
    float* stage  = reinterpret_cast<float*>(smem + SM_STG);

    // bias staging: [13][64]
    for (int i = tid; i < 832; i += 128) {
        int c = i >> 6, j = i & 63;
        float b;
        if (c < 4)       b = bq[i];
        else if (c < 8)  b = bk[i - 256];
        else if (c < 12) b = bv[i - 512];
        else             b = bs[j];
        biasSm[i] = b;
    }

    // A load + bf16 hi/lo split into smem [128][LDA]
#pragma unroll
    for (int j = 0; j < 16; j++) {
        int idx = tid + j * 128;
        int r = idx >> 4, c4 = idx & 15;
        int gr = row0 + r;
        float4 xv = make_float4(0.f, 0.f, 0.f, 0.f);
        if (gr < nrows)
            xv = *reinterpret_cast<const float4*>(X + (size_t)gr * 64 + c4 * 4);
        __nv_bfloat16 h0 = __float2bfloat16(xv.x);
        __nv_bfloat16 h1 = __float2bfloat16(xv.y);
        __nv_bfloat16 h2 = __float2bfloat16(xv.z);
        __nv_bfloat16 h3 = __float2bfloat16(xv.w);
        __nv_bfloat162 hh0; hh0.x = h0; hh0.y = h1;
        __nv_bfloat162 hh1; hh1.x = h2; hh1.y = h3;
        __nv_bfloat162 ll0 = __floats2bfloat162_rn(xv.x - __bfloat162float(h0),
                                                   xv.y - __bfloat162float(h1));
        __nv_bfloat162 ll1 = __floats2bfloat162_rn(xv.z - __bfloat162float(h2),
                                                   xv.w - __bfloat162float(h3));
        uint2 uh, ul;
        uh.x = *reinterpret_cast<unsigned*>(&hh0);
        uh.y = *reinterpret_cast<unsigned*>(&hh1);
        ul.x = *reinterpret_cast<unsigned*>(&ll0);
        ul.y = *reinterpret_cast<unsigned*>(&ll1);
        size_t boff = (size_t)(r * LDA + c4 * 4) * 2;
        *reinterpret_cast<uint2*>(smem + SM_AHI + boff) = uh;
        *reinterpret_cast<uint2*>(smem + SM_ALO + boff) = ul;
    }

    // lane-fixed fragment address components
    int arow = w * 32 + (l & 15);
    int acol = (l >> 4) * 8;
    int bn   = (l & 7) + ((l >> 4) << 3);
    int bk8  = (l & 8);

    // ---- register prefetch of B chunk 0 (8 x uint4 per thread = 16KB) ----
    uint4 pre[8];
#pragma unroll
    for (int j = 0; j < 8; j++)
        pre[j] = reinterpret_cast<const uint4*>(wb)[tid + j * 128];

    for (int c = 0; c < 13; c++) {
        // ---- publish prefetched B chunk into smem [64][LDB] (hi then lo) ----
#pragma unroll
        for (int j = 0; j < 8; j++) {
            int i = tid + j * 128;
            int part = i >> 9, jj = i & 511;
            int n = jj >> 3, k8 = jj & 7;
            char* p = smem + (part ? SM_BLO : SM_BHI) + n * (LDB * 2) + k8 * 16;
            *reinterpret_cast<uint2*>(p)     = make_uint2(pre[j].x, pre[j].y);
            *reinterpret_cast<uint2*>(p + 8) = make_uint2(pre[j].z, pre[j].w);
        }
        __syncthreads();

        // ---- issue LDGs for next chunk (overlap with MMA) ----
        if (c + 1 < 13) {
#pragma unroll
            for (int j = 0; j < 8; j++)
                pre[j] = reinterpret_cast<const uint4*>(wb + (size_t)(c + 1) * 8192)[tid + j * 128];
        }

        float acc[2][8][4];
#pragma unroll
        for (int mt = 0; mt < 2; mt++)
#pragma unroll
            for (int nt = 0; nt < 8; nt++)
#pragma unroll
                for (int q = 0; q < 4; q++) acc[mt][nt][q] = 0.f;

#pragma unroll
        for (int kt = 0; kt < 4; kt++) {
            uint32_t ah[2][4], al[2][4];
#pragma unroll
            for (int mt = 0; mt < 2; mt++) {
                uint32_t off = (uint32_t)(((arow + mt * 16) * LDA + kt * 16 + acol) * 2);
                LDMX4(ah[mt][0], ah[mt][1], ah[mt][2], ah[mt][3], sb + SM_AHI + off);
                LDMX4(al[mt][0], al[mt][1], al[mt][2], al[mt][3], sb + SM_ALO + off);
            }
            uint32_t bh[4][4], bl[4][4];
#pragma unroll
            for (int np = 0; np < 4; np++) {
                uint32_t off = (uint32_t)(((bn + np * 16) * LDB + kt * 16 + bk8) * 2);
                LDMX4(bh[np][0], bh[np][1], bh[np][2], bh[np][3], sb + SM_BHI + off);
                LDMX4(bl[np][0], bl[np][1], bl[np][2], bl[np][3], sb + SM_BLO + off);
            }
#pragma unroll
            for (int mt = 0; mt < 2; mt++) {
#pragma unroll
                for (int np = 0; np < 4; np++) {
                    MMA16816(acc[mt][np * 2],     ah[mt], bh[np][0], bh[np][1]);
                    MMA16816(acc[mt][np * 2],     ah[mt], bl[np][0], bl[np][1]);
                    MMA16816(acc[mt][np * 2],     al[mt], bh[np][0], bh[np][1]);
                    MMA16816(acc[mt][np * 2 + 1], ah[mt], bh[np][2], bh[np][3]);
                    MMA16816(acc[mt][np * 2 + 1], ah[mt], bl[np][2], bl[np][3]);
                    MMA16816(acc[mt][np * 2 + 1], al[mt], bh[np][2], bh[np][3]);
                }
            }
        }

        // ---- stage accumulators to smem ----
        int rs = w * 32 + (l >> 2);
        int cs = (l & 3) * 2;
#pragma unroll
        for (int mt = 0; mt < 2; mt++) {
#pragma unroll
            for (int nt = 0; nt < 8; nt++) {
                int col = nt * 8 + cs;
                *reinterpret_cast<float2*>(stage + (rs + mt * 16) * STG + col) =
                    make_float2(acc[mt][nt][0], acc[mt][nt][1]);
                *reinterpret_cast<float2*>(stage + (rs + mt * 16 + 8) * STG + col) =
                    make_float2(acc[mt][nt][2], acc[mt][nt][3]);
            }
        }
        __syncthreads();

        // ---- coalesced typed store ----
#pragma unroll
        for (int j = 0; j < 16; j++) {
            int idx = tid + j * 128;
            int r = idx >> 4, c4 = idx & 15;
            int gr = row0 + r;
            if (gr >= nrows) continue;
            float4 o = *reinterpret_cast<const float4*>(stage + r * STG + c4 * 4);
            const float4 bb = *reinterpret_cast<const float4*>(biasSm + c * 64 + c4 * 4);
            o.x += bb.x; o.y += bb.y; o.z += bb.z; o.w += bb.w;
            if (c < 4) {
                *reinterpret_cast<float4*>(g_q + (size_t)gr * 256 + c * 64 + c4 * 4) = o;
            } else if (c < 12) {
                int col0 = (c < 8) ? (c - 4) * 64 : (c - 8) * 64 + 256;
                __nv_bfloat162 p0 = __floats2bfloat162_rn(o.x, o.y);
                __nv_bfloat162 p1 = __floats2bfloat162_rn(o.z, o.w);
                uint2 u;
                u.x = *reinterpret_cast<unsigned*>(&p0);
                u.y = *reinterpret_cast<unsigned*>(&p1);
                *reinterpret_cast<uint2*>(g_kv + (size_t)gr * 512 + col0 + c4 * 4) = u;
            } else {
                *reinterpret_cast<float4*>(g_skip + (size_t)gr * 64 + c4 * 4) = o;
            }
        }
        __syncthreads();
    }
}

// ====== fused attention + epilogue: one warp per destination node (R7 exact) ======
__device__ __forceinline__ float2 bf2f(unsigned u) {
    __nv_bfloat162 t = *reinterpret_cast<__nv_bfloat162*>(&u);
    return __bfloat1622float2(t);
}

__global__ void __launch_bounds__(256) attn_kernel(float* __restrict__ out_ext,
                                                   int to_gh, int relu,
                                                   int n_base, int n_cnt) {
    int n = n_base + ((blockIdx.x * blockDim.x + threadIdx.x) >> 5);
    if (n >= n_base + n_cnt) return;
    int lane = threadIdx.x & 31;
    int h = lane >> 3, m = lane & 7;

    size_t qbase = (size_t)n * HC + h * 64 + m * 8;
    float4 q0 = *reinterpret_cast<const float4*>(g_q + qbase);
    float4 q1 = *reinterpret_cast<const float4*>(g_q + qbase + 4);

    float acc[8] = {0.f, 0.f, 0.f, 0.f, 0.f, 0.f, 0.f, 0.f};
    float den = 0.f;

    const uint4* kvp = reinterpret_cast<const uint4*>(g_kv);  // node stride 64 uint4
    int koff = h * 8 + m;

    int e0 = g_indptr[n], e1 = g_indptr[n + 1];
    int e = e0;

    // ---- 2-edge unrolled main loop (dual ILP chains) ----
    for (; e + 2 <= e1; e += 2) {
        int sA = g_col[e], sB = g_col[e + 1];
        uint4 krA = kvp[(size_t)sA * 64 + koff];
        uint4 krB = kvp[(size_t)sB * 64 + koff];
        uint4 vrA = kvp[(size_t)sA * 64 + 32 + koff];
        uint4 vrB = kvp[(size_t)sB * 64 + 32 + koff];

        float2 a0 = bf2f(krA.x), a1 = bf2f(krA.y), a2 = bf2f(krA.z), a3 = bf2f(krA.w);
        float2 c0 = bf2f(krB.x), c1 = bf2f(krB.y), c2 = bf2f(krB.z), c3 = bf2f(krB.w);
        float pA = q0.x * a0.x + q0.y * a0.y + q0.z * a1.x + q0.w * a1.y
                 + q1.x * a2.x + q1.y * a2.y + q1.z * a3.x + q1.w * a3.y;
        float pB = q0.x * c0.x + q0.y * c0.y + q0.z * c1.x + q0.w * c1.y
                 + q1.x * c2.x + q1.y * c2.y + q1.z * c3.x + q1.w * c3.y;
        pA += __shfl_xor_sync(0xffffffffu, pA, 1);
        pB += __shfl_xor_sync(0xffffffffu, pB, 1);
        pA += __shfl_xor_sync(0xffffffffu, pA, 2);
        pB += __shfl_xor_sync(0xffffffffu, pB, 2);
        pA += __shfl_xor_sync(0xffffffffu, pA, 4);
        pB += __shfl_xor_sync(0xffffffffu, pB, 4);
        float exA = __expf(pA * 0.125f);
        float exB = __expf(pB * 0.125f);

        float2 vA0 = bf2f(vrA.x), vA1 = bf2f(vrA.y), vA2 = bf2f(vrA.z), vA3 = bf2f(vrA.w);
        float2 vB0 = bf2f(vrB.x), vB1 = bf2f(vrB.y), vB2 = bf2f(vrB.z), vB3 = bf2f(vrB.w);
        acc[0] += exA * vA0.x + exB * vB0.x;
        acc[1] += exA * vA0.y + exB * vB0.y;
        acc[2] += exA * vA1.x + exB * vB1.x;
        acc[3] += exA * vA1.y + exB * vB1.y;
        acc[4] += exA * vA2.x + exB * vB2.x;
        acc[5] += exA * vA2.y + exB * vB2.y;
        acc[6] += exA * vA3.x + exB * vB3.x;
        acc[7] += exA * vA3.y + exB * vB3.y;
        den += exA + exB;
    }
    // ---- tail edge ----
    if (e < e1) {
        int s = g_col[e];
        uint4 kr = kvp[(size_t)s * 64 + koff];
        uint4 vr = kvp[(size_t)s * 64 + 32 + koff];
        float2 k0 = bf2f(kr.x), k1 = bf2f(kr.y), k2 = bf2f(kr.z), k3 = bf2f(kr.w);
        float p = q0.x * k0.x + q0.y * k0.y + q0.z * k1.x + q0.w * k1.y
                + q1.x * k2.x + q1.y * k2.y + q1.z * k3.x + q1.w * k3.y;
        p += __shfl_xor_sync(0xffffffffu, p, 1);
        p += __shfl_xor_sync(0xffffffffu, p, 2);
        p += __shfl_xor_sync(0xffffffffu, p, 4);
        float ex = __expf(p * 0.125f);
        float2 v0 = bf2f(vr.x), v1 = bf2f(vr.y), v2 = bf2f(vr.z), v3 = bf2f(vr.w);
        acc[0] += ex * v0.x; acc[1] += ex * v0.y;
        acc[2] += ex * v1.x; acc[3] += ex * v1.y;
        acc[4] += ex * v2.x; acc[5] += ex * v2.y;
        acc[6] += ex * v3.x; acc[7] += ex * v3.y;
        den += ex;
    }

    float inv = 1.0f / (den + 1e-16f);
#pragma unroll
    for (int j = 0; j < 8; j++) {
        float r = acc[j] * inv;
        r += __shfl_xor_sync(0xffffffffu, r, 8);
        r += __shfl_xor_sync(0xffffffffu, r, 16);
        acc[j] = r * 0.25f;
    }

    if (h == 0) {
        float* out = to_gh ? g_h : out_ext;
        size_t ob = (size_t)n * DD + m * 8;
        float4 s0 = *reinterpret_cast<const float4*>(g_skip + ob);
        float4 s1 = *reinterpret_cast<const float4*>(g_skip + ob + 4);
        float4 o0, o1;
        o0.x = acc[0] + s0.x; o0.y = acc[1] + s0.y;
        o0.z = acc[2] + s0.z; o0.w = acc[3] + s0.w;
        o1.x = acc[4] + s1.x; o1.y = acc[5] + s1.y;
        o1.z = acc[6] + s1.z; o1.w = acc[7] + s1.w;
        if (relu) {
            o0.x = fmaxf(o0.x, 0.f); o0.y = fmaxf(o0.y, 0.f);
            o0.z = fmaxf(o0.z, 0.f); o0.w = fmaxf(o0.w, 0.f);
            o1.x = fmaxf(o1.x, 0.f); o1.y = fmaxf(o1.y, 0.f);
            o1.z = fmaxf(o1.z, 0.f); o1.w = fmaxf(o1.w, 0.f);
        }
        *reinterpret_cast<float4*>(out + ob)     = o0;
        *reinterpret_cast<float4*>(out + ob + 4) = o1;
    }
}

extern "C" void kernel_launch(void* const* d_in, const int* in_sizes, int n_in,
                              void* d_out, int out_size) {
    const float* x   = (const float*)d_in[0];
    const int*   ei  = (const int*)d_in[1];
    const float* Wq1 = (const float*)d_in[2];
    const float* bq1 = (const float*)d_in[3];
    const float* Wk1 = (const float*)d_in[4];
    const float* bk1 = (const float*)d_in[5];
    const float* Wv1 = (const float*)d_in[6];
    const float* bv1 = (const float*)d_in[7];
    const float* Ws1 = (const float*)d_in[8];
    const float* bs1 = (const float*)d_in[9];
    const float* Wq2 = (const float*)d_in[10];
    const float* bq2 = (const float*)d_in[11];
    const float* Wk2 = (const float*)d_in[12];
    const float* bk2 = (const float*)d_in[13];
    const float* Wv2 = (const float*)d_in[14];
    const float* bv2 = (const float*)d_in[15];
    const float* Ws2 = (const float*)d_in[16];
    const float* bs2 = (const float*)d_in[17];
    float* out = (float*)d_out;

    // one-time host-side setup (runs on the eager correctness call, before capture)
    static cudaStream_t s_side = nullptr;
    static cudaEvent_t ev_root = nullptr, ev_g1 = nullptr, ev_pw2 = nullptr,
                       ev_a1 = nullptr, ev_g2a = nullptr;
    if (!s_side) {
        cudaStreamCreateWithFlags(&s_side, cudaStreamNonBlocking);
        cudaEventCreateWithFlags(&ev_root, cudaEventDisableTiming);
        cudaEventCreateWithFlags(&ev_g1,   cudaEventDisableTiming);
        cudaEventCreateWithFlags(&ev_pw2,  cudaEventDisableTiming);
        cudaEventCreateWithFlags(&ev_a1,   cudaEventDisableTiming);
        cudaEventCreateWithFlags(&ev_g2a,  cudaEventDisableTiming);
        cudaFuncSetAttribute(tc_gemm, cudaFuncAttributeMaxDynamicSharedMemorySize, SM_TOT);
    }

    __nv_bfloat16* wb_dev = nullptr;
    cudaGetSymbolAddress((void**)&wb_dev, g_wb);
    __nv_bfloat16* wb2 = wb_dev + 13 * 8192;

    int scan_blocks = (NN + 255) / 256;   // 391
    const int A_CNT = HALF_ROWS;          // 50048 nodes in half A
    const int B_CNT = NN - HALF_ROWS;     // 49952 nodes in half B
    int attnA_blocks = (A_CNT * 32 + 255) / 256;
    int attnB_blocks = (B_CNT * 32 + 255) / 256;
    int attnF_blocks = (NN * 32 + 255) / 256;

    // ---- fork: prep_w1 + gemm1 (side stream) || CSR build (main stream) ----
    cudaEventRecord(ev_root, 0);
    cudaStreamWaitEvent(s_side, ev_root, 0);

    // side stream: layer-1 weight prep + layer-1 GEMM (depends only on x, weights)
    prep_w<<<13, 256, 0, s_side>>>(Wq1, Wk1, Wv1, Ws1, wb_dev);
    tc_gemm<<<GEMM_BLKS, 128, SM_TOT, s_side>>>(x, 0, bq1, bk1, bv1, bs1, wb_dev, NN, 0);
    cudaEventRecord(ev_g1, s_side);
    // layer-2 weight prep: off critical path (runs during attn1A)
    prep_w<<<13, 256, 0, s_side>>>(Wq2, Wk2, Wv2, Ws2, wb2);
    cudaEventRecord(ev_pw2, s_side);

    // main stream: CSR by destination (depends only on edge_index)
    zero_cnt_kernel<<<(NN + 255) / 256, 256>>>();
    hist_kernel<<<(EE + 255) / 256, 256>>>(ei);
    scan_local<<<scan_blocks, 256>>>();
    scan_bsums<<<1, 512>>>(scan_blocks);
    scan_add<<<scan_blocks, 256>>>();
    scatter_kernel<<<(EE + 255) / 256, 256>>>(ei);

    // join: attn1 needs CSR (main) + gemm1 (side)
    cudaStreamWaitEvent(0, ev_g1, 0);

    // ---- layer-1 attention half A, then pipeline gemm2(A) || attn1(B) ----
    attn_kernel<<<attnA_blocks, 256>>>(nullptr, 1, 1, 0, A_CNT);
    cudaEventRecord(ev_a1, 0);

    // side stream: gemm2 over rows of half A (g_h rows written by attn1A)
    cudaStreamWaitEvent(s_side, ev_a1, 0);
    tc_gemm<<<HALF_BLKS, 128, SM_TOT, s_side>>>(nullptr, 1, bq2, bk2, bv2, bs2, wb2, NN, 0);
    cudaEventRecord(ev_g2a, s_side);

    // main stream: attn1 half B (concurrent with gemm2A)
    attn_kernel<<<attnB_blocks, 256>>>(nullptr, 1, 1, A_CNT, B_CNT);
    // gemm2 half B (needs prep_w2 + attn1B; prep_w2 long done)
    cudaStreamWaitEvent(0, ev_pw2, 0);
    tc_gemm<<<GEMM_BLKS - HALF_BLKS, 128, SM_TOT>>>(nullptr, 1, bq2, bk2, bv2, bs2, wb2, NN, HALF_BLKS);

    // join gemm2A, then full layer-2 attention
    cudaStreamWaitEvent(0, ev_g2a, 0);
    attn_kernel<<<attnF_blocks, 256>>>(out, 0, 0, 0, NN);
}

// round 13
// speedup vs baseline: 1.0303x; 1.0303x over previous
#include <cuda_runtime.h>
#include <cuda_bf16.h>
#include <cstdint>

#define NN 100000
#define EE 800000
#define DD 64
#define HH 4
#define HC 256

// ---- scratch (static device globals: allocation-free) ----
__device__ __nv_bfloat16 g_qb[(size_t)NN * HC];        // bf16 Q  [N][256]
__device__ __nv_bfloat16 g_kv[(size_t)NN * 512];       // bf16 K||V per node: [N][512]
__device__ float g_skip[(size_t)NN * DD];
__device__ float g_h[(size_t)NN * DD];
__device__ int   g_cnt[NN];
__device__ int   g_indptr[NN + 1];
__device__ int   g_cursor[NN];
__device__ int   g_col[EE];
__device__ int   g_bsum[512];
__device__ int   g_boff[512];
// W in bf16 hi/lo, transposed: [layer][chunk 13][part 2][n 64][k 64]
__device__ __nv_bfloat16 g_wb[2 * 13 * 2 * 64 * 64];

__device__ __forceinline__ uint32_t smem_u32(const void* p) {
    uint32_t a;
    asm("{ .reg .u64 t; cvta.to.shared.u64 t, %1; cvt.u32.u64 %0, t; }" : "=r"(a) : "l"(p));
    return a;
}

#define LDMX4(d0, d1, d2, d3, a) \
    asm volatile("ldmatrix.sync.aligned.m8n8.x4.shared.b16 {%0,%1,%2,%3}, [%4];" \
                 : "=r"(d0), "=r"(d1), "=r"(d2), "=r"(d3) : "r"(a))

#define MMA16816(c, a, b0, b1) \
    asm volatile("mma.sync.aligned.m16n8k16.row.col.f32.bf16.bf16.f32 " \
                 "{%0,%1,%2,%3}, {%4,%5,%6,%7}, {%8,%9}, {%0,%1,%2,%3};" \
                 : "+f"((c)[0]), "+f"((c)[1]), "+f"((c)[2]), "+f"((c)[3]) \
                 : "r"((a)[0]), "r"((a)[1]), "r"((a)[2]), "r"((a)[3]), "r"(b0), "r"(b1))

// ================= CSR build (per call, deterministic input) =================
__global__ void zero_cnt_kernel() {
    int i = blockIdx.x * blockDim.x + threadIdx.x;
    if (i < NN) g_cnt[i] = 0;
}
__global__ void hist_kernel(const int* __restrict__ ei) {
    int e = blockIdx.x * blockDim.x + threadIdx.x;
    if (e < EE) atomicAdd(&g_cnt[ei[EE + e]], 1);
}

// ---- hierarchical scan ----
__global__ void __launch_bounds__(256) scan_local() {
    __shared__ int s_w[8];
    int tid = threadIdx.x, lane = tid & 31, wid = tid >> 5;
    int i = blockIdx.x * 256 + tid;
    int v = (i < NN) ? g_cnt[i] : 0;
    int x = v;
#pragma unroll
    for (int d = 1; d < 32; d <<= 1) {
        int t = __shfl_up_sync(0xffffffffu, x, d);
        if (lane >= d) x += t;
    }
    if (lane == 31) s_w[wid] = x;
    __syncthreads();
    if (wid == 0 && lane < 8) {
        int y = s_w[lane];
#pragma unroll
        for (int d = 1; d < 8; d <<= 1) {
            int t = __shfl_up_sync(0xffu, y, d);
            if (lane >= d) y += t;
        }
        s_w[lane] = y;
    }
    __syncthreads();
    int excl = (wid > 0 ? s_w[wid - 1] : 0) + x - v;
    if (i < NN) g_indptr[i] = excl;
    if (tid == 255) g_bsum[blockIdx.x] = s_w[7];
}

__global__ void __launch_bounds__(512) scan_bsums(int nblocks) {
    __shared__ int s_w[16];
    int tid = threadIdx.x, lane = tid & 31, wid = tid >> 5;
    int v = (tid < nblocks) ? g_bsum[tid] : 0;
    int x = v;
#pragma unroll
    for (int d = 1; d < 32; d <<= 1) {
        int t = __shfl_up_sync(0xffffffffu, x, d);
        if (lane >= d) x += t;
    }
    if (lane == 31) s_w[wid] = x;
    __syncthreads();
    if (wid == 0 && lane < 16) {
        int y = s_w[lane];
#pragma unroll
        for (int d = 1; d < 16; d <<= 1) {
            int t = __shfl_up_sync(0xffffu, y, d);
            if (lane >= d) y += t;
        }
        s_w[lane] = y;
    }
    __syncthreads();
    int excl = (wid > 0 ? s_w[wid - 1] : 0) + x - v;
    if (tid < nblocks) g_boff[tid] = excl;
}

__global__ void __launch_bounds__(256) scan_add() {
    int i = blockIdx.x * 256 + threadIdx.x;
    if (i < NN) {
        int val = g_indptr[i] + g_boff[blockIdx.x];
        g_indptr[i] = val;
        g_cursor[i] = val;
    }
    if (i == 0) g_indptr[NN] = EE;
}

__global__ void scatter_kernel(const int* __restrict__ ei) {
    int e = blockIdx.x * blockDim.x + threadIdx.x;
    if (e < EE) {
        int d = ei[EE + e];
        int pos = atomicAdd(&g_cursor[d], 1);
        g_col[pos] = ei[e];
    }
}

// ============ W prep: transpose + bf16 hi/lo split (both layers) ============
__global__ void prep_w(const float* __restrict__ Wq1, const float* __restrict__ Wk1,
                       const float* __restrict__ Wv1, const float* __restrict__ Ws1,
                       const float* __restrict__ Wq2, const float* __restrict__ Wk2,
                       const float* __restrict__ Wv2, const float* __restrict__ Ws2,
                       __nv_bfloat16* __restrict__ dst0) {
    int b = blockIdx.x;           // 0..25
    int layer = b / 13, c = b % 13;
    const float* Wq = layer ? Wq2 : Wq1;
    const float* Wk = layer ? Wk2 : Wk1;
    const float* Wv = layer ? Wv2 : Wv1;
    const float* Ws = layer ? Ws2 : Ws1;
    __nv_bfloat16* dst = dst0 + (size_t)layer * 13 * 8192;
    for (int i = threadIdx.x; i < 4096; i += 256) {
        int n = i >> 6, k = i & 63;
        float w;
        if (c < 4)       w = Wq[k * 256 + c * 64 + n];
        else if (c < 8)  w = Wk[k * 256 + (c - 4) * 64 + n];
        else if (c < 12) w = Wv[k * 256 + (c - 8) * 64 + n];
        else             w = Ws[k * 64 + n];
        __nv_bfloat16 hi = __float2bfloat16(w);
        float lo = w - __bfloat162float(hi);
        dst[c * 8192 + i]        = hi;
        dst[c * 8192 + 4096 + i] = __float2bfloat16(lo);
    }
}

// ============ mma.sync GEMM: 128 rows x 832 cols, bf16x3 split ============
#define SM_BIAS 0
#define SM_AHI  3584
#define SM_ALO  22016
#define SM_BHI  40448
#define SM_BLO  49664
#define SM_STG  58880
#define SM_TOT  93696
#define LDA 72
#define LDB 72
#define STG 68

__global__ void __launch_bounds__(128) tc_gemm(
    const float* __restrict__ Xext, int useGh,
    const float* __restrict__ bq, const float* __restrict__ bk,
    const float* __restrict__ bv, const float* __restrict__ bs,
    const __nv_bfloat16* __restrict__ wb, int nrows)
{
    extern __shared__ char smem[];
    uint32_t sb = smem_u32(smem);
    const float* X = useGh ? g_h : Xext;
    int tid = threadIdx.x, w = tid >> 5, l = tid & 31;
    int row0 = blockIdx.x * 128;
    float* biasSm = reinterpret_cast<float*>(smem + SM_BIAS);
    float* stage  = reinterpret_cast<float*>(smem + SM_STG);

    for (int i = tid; i < 832; i += 128) {
        int c = i >> 6, j = i & 63;
        float b;
        if (c < 4)       b = bq[i];
        else if (c < 8)  b = bk[i - 256];
        else if (c < 12) b = bv[i - 512];
        else             b = bs[j];
        biasSm[i] = b;
    }

#pragma unroll
    for (int j = 0; j < 16; j++) {
        int idx = tid + j * 128;
        int r = idx >> 4, c4 = idx & 15;
        int gr = row0 + r;
        float4 xv = make_float4(0.f, 0.f, 0.f, 0.f);
        if (gr < nrows)
            xv = *reinterpret_cast<const float4*>(X + (size_t)gr * 64 + c4 * 4);
        __nv_bfloat16 h0 = __float2bfloat16(xv.x);
        __nv_bfloat16 h1 = __float2bfloat16(xv.y);
        __nv_bfloat16 h2 = __float2bfloat16(xv.z);
        __nv_bfloat16 h3 = __float2bfloat16(xv.w);
        __nv_bfloat162 hh0; hh0.x = h0; hh0.y = h1;
        __nv_bfloat162 hh1; hh1.x = h2; hh1.y = h3;
        __nv_bfloat162 ll0 = __floats2bfloat162_rn(xv.x - __bfloat162float(h0),
                                                   xv.y - __bfloat162float(h1));
        __nv_bfloat162 ll1 = __floats2bfloat162_rn(xv.z - __bfloat162float(h2),
                                                   xv.w - __bfloat162float(h3));
        uint2 uh, ul;
        uh.x = *reinterpret_cast<unsigned*>(&hh0);
        uh.y = *reinterpret_cast<unsigned*>(&hh1);
        ul.x = *reinterpret_cast<unsigned*>(&ll0);
        ul.y = *reinterpret_cast<unsigned*>(&ll1);
        size_t boff = (size_t)(r * LDA + c4 * 4) * 2;
        *reinterpret_cast<uint2*>(smem + SM_AHI + boff) = uh;
        *reinterpret_cast<uint2*>(smem + SM_ALO + boff) = ul;
    }

    int arow = w * 32 + (l & 15);
    int acol = (l >> 4) * 8;
    int bn   = (l & 7) + ((l >> 4) << 3);
    int bk8  = (l & 8);

    uint4 pre[8];
#pragma unroll
    for (int j = 0; j < 8; j++)
        pre[j] = reinterpret_cast<const uint4*>(wb)[tid + j * 128];

    for (int c = 0; c < 13; c++) {
#pragma unroll
        for (int j = 0; j < 8; j++) {
            int i = tid + j * 128;
            int part = i >> 9, jj = i & 511;
            int n = jj >> 3, k8 = jj & 7;
            char* p = smem + (part ? SM_BLO : SM_BHI) + n * (LDB * 2) + k8 * 16;
            *reinterpret_cast<uint2*>(p)     = make_uint2(pre[j].x, pre[j].y);
            *reinterpret_cast<uint2*>(p + 8) = make_uint2(pre[j].z, pre[j].w);
        }
        __syncthreads();

        if (c + 1 < 13) {
#pragma unroll
            for (int j = 0; j < 8; j++)
                pre[j] = reinterpret_cast<const uint4*>(wb + (size_t)(c + 1) * 8192)[tid + j * 128];
        }

        float acc[2][8][4];
#pragma unroll
        for (int mt = 0; mt < 2; mt++)
#pragma unroll
            for (int nt = 0; nt < 8; nt++)
#pragma unroll
                for (int q = 0; q < 4; q++) acc[mt][nt][q] = 0.f;

#pragma unroll
        for (int kt = 0; kt < 4; kt++) {
            uint32_t ah[2][4], al[2][4];
#pragma unroll
            for (int mt = 0; mt < 2; mt++) {
                uint32_t off = (uint32_t)(((arow + mt * 16) * LDA + kt * 16 + acol) * 2);
                LDMX4(ah[mt][0], ah[mt][1], ah[mt][2], ah[mt][3], sb + SM_AHI + off);
                LDMX4(al[mt][0], al[mt][1], al[mt][2], al[mt][3], sb + SM_ALO + off);
            }
            uint32_t bh[4][4], bl[4][4];
#pragma unroll
            for (int np = 0; np < 4; np++) {
                uint32_t off = (uint32_t)(((bn + np * 16) * LDB + kt * 16 + bk8) * 2);
                LDMX4(bh[np][0], bh[np][1], bh[np][2], bh[np][3], sb + SM_BHI + off);
                LDMX4(bl[np][0], bl[np][1], bl[np][2], bl[np][3], sb + SM_BLO + off);
            }
#pragma unroll
            for (int mt = 0; mt < 2; mt++) {
#pragma unroll
                for (int np = 0; np < 4; np++) {
                    MMA16816(acc[mt][np * 2],     ah[mt], bh[np][0], bh[np][1]);
                    MMA16816(acc[mt][np * 2],     ah[mt], bl[np][0], bl[np][1]);
                    MMA16816(acc[mt][np * 2],     al[mt], bh[np][0], bh[np][1]);
                    MMA16816(acc[mt][np * 2 + 1], ah[mt], bh[np][2], bh[np][3]);
                    MMA16816(acc[mt][np * 2 + 1], ah[mt], bl[np][2], bl[np][3]);
                    MMA16816(acc[mt][np * 2 + 1], al[mt], bh[np][2], bh[np][3]);
                }
            }
        }

        int rs = w * 32 + (l >> 2);
        int cs = (l & 3) * 2;
#pragma unroll
        for (int mt = 0; mt < 2; mt++) {
#pragma unroll
            for (int nt = 0; nt < 8; nt++) {
                int col = nt * 8 + cs;
                *reinterpret_cast<float2*>(stage + (rs + mt * 16) * STG + col) =
                    make_float2(acc[mt][nt][0], acc[mt][nt][1]);
                *reinterpret_cast<float2*>(stage + (rs + mt * 16 + 8) * STG + col) =
                    make_float2(acc[mt][nt][2], acc[mt][nt][3]);
            }
        }
        __syncthreads();

#pragma unroll
        for (int j = 0; j < 16; j++) {
            int idx = tid + j * 128;
            int r = idx >> 4, c4 = idx & 15;
            int gr = row0 + r;
            if (gr >= nrows) continue;
            float4 o = *reinterpret_cast<const float4*>(stage + r * STG + c4 * 4);
            const float4 bb = *reinterpret_cast<const float4*>(biasSm + c * 64 + c4 * 4);
            o.x += bb.x; o.y += bb.y; o.z += bb.z; o.w += bb.w;
            if (c < 12) {
                __nv_bfloat162 p0 = __floats2bfloat162_rn(o.x, o.y);
                __nv_bfloat162 p1 = __floats2bfloat162_rn(o.z, o.w);
                uint2 u;
                u.x = *reinterpret_cast<unsigned*>(&p0);
                u.y = *reinterpret_cast<unsigned*>(&p1);
                if (c < 4) {
                    *reinterpret_cast<uint2*>(g_qb + (size_t)gr * 256 + c * 64 + c4 * 4) = u;
                } else {
                    int col0 = (c < 8) ? (c - 4) * 64 : (c - 8) * 64 + 256;
                    *reinterpret_cast<uint2*>(g_kv + (size_t)gr * 512 + col0 + c4 * 4) = u;
                }
            } else {
                *reinterpret_cast<float4*>(g_skip + (size_t)gr * 64 + c4 * 4) = o;
            }
        }
        __syncthreads();
    }
}

// ====== fused attention + epilogue: one warp per destination node ======
__device__ __forceinline__ float2 bf2f(unsigned u) {
    __nv_bfloat162 t = *reinterpret_cast<__nv_bfloat162*>(&u);
    return __bfloat1622float2(t);
}

__global__ void __launch_bounds__(256) attn_kernel(float* __restrict__ out_ext,
                                                   int to_gh, int relu) {
    int n = (blockIdx.x * blockDim.x + threadIdx.x) >> 5;
    if (n >= NN) return;
    int lane = threadIdx.x & 31;
    int h = lane >> 3, m = lane & 7;
    int koff = h * 8 + m;

    // decode bf16 q once per node
    uint4 qr = reinterpret_cast<const uint4*>(g_qb)[(size_t)n * 32 + koff];
    float2 t0 = bf2f(qr.x), t1 = bf2f(qr.y), t2 = bf2f(qr.z), t3 = bf2f(qr.w);
    float4 q0 = make_float4(t0.x, t0.y, t1.x, t1.y);
    float4 q1 = make_float4(t2.x, t2.y, t3.x, t3.y);

    float acc[8] = {0.f, 0.f, 0.f, 0.f, 0.f, 0.f, 0.f, 0.f};
    float den = 0.f;

    const uint4* kvp = reinterpret_cast<const uint4*>(g_kv);  // node stride 64 uint4

    int e0 = g_indptr[n], e1 = g_indptr[n + 1];
    int e = e0;

    // ---- 2-edge unrolled main loop (dual ILP chains) ----
    for (; e + 2 <= e1; e += 2) {
        int sA = g_col[e], sB = g_col[e + 1];
        uint4 krA = kvp[(size_t)sA * 64 + koff];
        uint4 krB = kvp[(size_t)sB * 64 + koff];
        uint4 vrA = kvp[(size_t)sA * 64 + 32 + koff];
        uint4 vrB = kvp[(size_t)sB * 64 + 32 + koff];

        float2 a0 = bf2f(krA.x), a1 = bf2f(krA.y), a2 = bf2f(krA.z), a3 = bf2f(krA.w);
        float2 c0 = bf2f(krB.x), c1 = bf2f(krB.y), c2 = bf2f(krB.z), c3 = bf2f(krB.w);
        float pA = q0.x * a0.x + q0.y * a0.y + q0.z * a1.x + q0.w * a1.y
                 + q1.x * a2.x + q1.y * a2.y + q1.z * a3.x + q1.w * a3.y;
        float pB = q0.x * c0.x + q0.y * c0.y + q0.z * c1.x + q0.w * c1.y
                 + q1.x * c2.x + q1.y * c2.y + q1.z * c3.x + q1.w * c3.y;
        pA += __shfl_xor_sync(0xffffffffu, pA, 1);
        pB += __shfl_xor_sync(0xffffffffu, pB, 1);
        pA += __shfl_xor_sync(0xffffffffu, pA, 2);
        pB += __shfl_xor_sync(0xffffffffu, pB, 2);
        pA += __shfl_xor_sync(0xffffffffu, pA, 4);
        pB += __shfl_xor_sync(0xffffffffu, pB, 4);
        float exA = __expf(pA * 0.125f);
        float exB = __expf(pB * 0.125f);

        float2 vA0 = bf2f(vrA.x), vA1 = bf2f(vrA.y), vA2 = bf2f(vrA.z), vA3 = bf2f(vrA.w);
        float2 vB0 = bf2f(vrB.x), vB1 = bf2f(vrB.y), vB2 = bf2f(vrB.z), vB3 = bf2f(vrB.w);
        acc[0] += exA * vA0.x + exB * vB0.x;
        acc[1] += exA * vA0.y + exB * vB0.y;
        acc[2] += exA * vA1.x + exB * vB1.x;
        acc[3] += exA * vA1.y + exB * vB1.y;
        acc[4] += exA * vA2.x + exB * vB2.x;
        acc[5] += exA * vA2.y + exB * vB2.y;
        acc[6] += exA * vA3.x + exB * vB3.x;
        acc[7] += exA * vA3.y + exB * vB3.y;
        den += exA + exB;
    }
    // ---- tail edge ----
    if (e < e1) {
        int s = g_col[e];
        uint4 kr = kvp[(size_t)s * 64 + koff];
        uint4 vr = kvp[(size_t)s * 64 + 32 + koff];
        float2 k0 = bf2f(kr.x), k1 = bf2f(kr.y), k2 = bf2f(kr.z), k3 = bf2f(kr.w);
        float p = q0.x * k0.x + q0.y * k0.y + q0.z * k1.x + q0.w * k1.y
                + q1.x * k2.x + q1.y * k2.y + q1.z * k3.x + q1.w * k3.y;
        p += __shfl_xor_sync(0xffffffffu, p, 1);
        p += __shfl_xor_sync(0xffffffffu, p, 2);
        p += __shfl_xor_sync(0xffffffffu, p, 4);
        float ex = __expf(p * 0.125f);
        float2 v0 = bf2f(vr.x), v1 = bf2f(vr.y), v2 = bf2f(vr.z), v3 = bf2f(vr.w);
        acc[0] += ex * v0.x; acc[1] += ex * v0.y;
        acc[2] += ex * v1.x; acc[3] += ex * v1.y;
        acc[4] += ex * v2.x; acc[5] += ex * v2.y;
        acc[6] += ex * v3.x; acc[7] += ex * v3.y;
        den += ex;
    }

    float inv = 1.0f / (den + 1e-16f);
#pragma unroll
    for (int j = 0; j < 8; j++) {
        float r = acc[j] * inv;
        r += __shfl_xor_sync(0xffffffffu, r, 8);
        r += __shfl_xor_sync(0xffffffffu, r, 16);
        acc[j] = r * 0.25f;
    }

    if (h == 0) {
        float* out = to_gh ? g_h : out_ext;
        size_t ob = (size_t)n * DD + m * 8;
        float4 s0 = *reinterpret_cast<const float4*>(g_skip + ob);
        float4 s1 = *reinterpret_cast<const float4*>(g_skip + ob + 4);
        float4 o0, o1;
        o0.x = acc[0] + s0.x; o0.y = acc[1] + s0.y;
        o0.z = acc[2] + s0.z; o0.w = acc[3] + s0.w;
        o1.x = acc[4] + s1.x; o1.y = acc[5] + s1.y;
        o1.z = acc[6] + s1.z; o1.w = acc[7] + s1.w;
        if (relu) {
            o0.x = fmaxf(o0.x, 0.f); o0.y = fmaxf(o0.y, 0.f);
            o0.z = fmaxf(o0.z, 0.f); o0.w = fmaxf(o0.w, 0.f);
            o1.x = fmaxf(o1.x, 0.f); o1.y = fmaxf(o1.y, 0.f);
            o1.z = fmaxf(o1.z, 0.f); o1.w = fmaxf(o1.w, 0.f);
        }
        *reinterpret_cast<float4*>(out + ob)     = o0;
        *reinterpret_cast<float4*>(out + ob + 4) = o1;
    }
}

extern "C" void kernel_launch(void* const* d_in, const int* in_sizes, int n_in,
                              void* d_out, int out_size) {
    const float* x   = (const float*)d_in[0];
    const int*   ei  = (const int*)d_in[1];
    const float* Wq1 = (const float*)d_in[2];
    const float* bq1 = (const float*)d_in[3];
    const float* Wk1 = (const float*)d_in[4];
    const float* bk1 = (const float*)d_in[5];
    const float* Wv1 = (const float*)d_in[6];
    const float* bv1 = (const float*)d_in[7];
    const float* Ws1 = (const float*)d_in[8];
    const float* bs1 = (const float*)d_in[9];
    const float* Wq2 = (const float*)d_in[10];
    const float* bq2 = (const float*)d_in[11];
    const float* Wk2 = (const float*)d_in[12];
    const float* bk2 = (const float*)d_in[13];
    const float* Wv2 = (const float*)d_in[14];
    const float* bv2 = (const float*)d_in[15];
    const float* Ws2 = (const float*)d_in[16];
    const float* bs2 = (const float*)d_in[17];
    float* out = (float*)d_out;

    // one-time host-side setup (runs on the eager correctness call, before capture)
    static cudaStream_t s_side = nullptr;
    static cudaEvent_t ev_root = nullptr, ev_side = nullptr;
    if (!s_side) {
        cudaStreamCreateWithFlags(&s_side, cudaStreamNonBlocking);
        cudaEventCreateWithFlags(&ev_root, cudaEventDisableTiming);
        cudaEventCreateWithFlags(&ev_side, cudaEventDisableTiming);
        cudaFuncSetAttribute(tc_gemm, cudaFuncAttributeMaxDynamicSharedMemorySize, SM_TOT);
    }

    __nv_bfloat16* wb_dev = nullptr;
    cudaGetSymbolAddress((void**)&wb_dev, g_wb);

    int scan_blocks = (NN + 255) / 256;   // 391
    int gemm_blocks = (NN + 127) / 128;
    int attn_blocks = (NN * 32 + 255) / 256;

    // ---- fork: prep_w + gemm1 (side stream) || CSR build (main stream) ----
    cudaEventRecord(ev_root, 0);
    cudaStreamWaitEvent(s_side, ev_root, 0);

    prep_w<<<26, 256, 0, s_side>>>(Wq1, Wk1, Wv1, Ws1, Wq2, Wk2, Wv2, Ws2, wb_dev);
    tc_gemm<<<gemm_blocks, 128, SM_TOT, s_side>>>(x, 0, bq1, bk1, bv1, bs1, wb_dev, NN);
    cudaEventRecord(ev_side, s_side);

    zero_cnt_kernel<<<(NN + 255) / 256, 256>>>();
    hist_kernel<<<(EE + 255) / 256, 256>>>(ei);
    scan_local<<<scan_blocks, 256>>>();
    scan_bsums<<<1, 512>>>(scan_blocks);
    scan_add<<<scan_blocks, 256>>>();
    scatter_kernel<<<(EE + 255) / 256, 256>>>(ei);

    cudaStreamWaitEvent(0, ev_side, 0);

    // ---- layer 1 attention, then layer 2 (serial dependencies) ----
    attn_kernel<<<attn_blocks, 256>>>(nullptr, /*to_gh=*/1, /*relu=*/1);
    tc_gemm<<<gemm_blocks, 128, SM_TOT>>>(nullptr, 1, bq2, bk2, bv2, bs2, wb_dev + 13 * 8192, NN);
    attn_kernel<<<attn_blocks, 256>>>(out, /*to_gh=*/0, /*relu=*/0);
}

// round 14
// speedup vs baseline: 1.1138x; 1.0810x over previous
#include <cuda_runtime.h>
#include <cuda_bf16.h>
#include <cstdint>

#define NN 100000
#define EE 800000
#define DD 64
#define HH 4
#define HC 256

// ---- scratch (static device globals: allocation-free) ----
__device__ __nv_bfloat16 g_qb[(size_t)NN * HC];        // bf16 Q  [N][256]
__device__ __nv_bfloat16 g_kv[(size_t)NN * 512];       // bf16 K||V per node: [N][512]
__device__ float g_skip[(size_t)NN * DD];
__device__ float g_h[(size_t)NN * DD];
__device__ int   g_cnt[NN];
__device__ int   g_indptr[NN + 1];
__device__ int   g_cursor[NN];
__device__ int   g_col[EE];
__device__ int   g_bsum[512];
__device__ int   g_boff[512];
// W in bf16 hi/lo, transposed: [layer][chunk 13][part 2][n 64][k 64]
__device__ __nv_bfloat16 g_wb[2 * 13 * 2 * 64 * 64];

__device__ __forceinline__ uint32_t smem_u32(const void* p) {
    uint32_t a;
    asm("{ .reg .u64 t; cvta.to.shared.u64 t, %1; cvt.u32.u64 %0, t; }" : "=r"(a) : "l"(p));
    return a;
}

#define LDMX4(d0, d1, d2, d3, a) \
    asm volatile("ldmatrix.sync.aligned.m8n8.x4.shared.b16 {%0,%1,%2,%3}, [%4];" \
                 : "=r"(d0), "=r"(d1), "=r"(d2), "=r"(d3) : "r"(a))

#define MMA16816(c, a, b0, b1) \
    asm volatile("mma.sync.aligned.m16n8k16.row.col.f32.bf16.bf16.f32 " \
                 "{%0,%1,%2,%3}, {%4,%5,%6,%7}, {%8,%9}, {%0,%1,%2,%3};" \
                 : "+f"((c)[0]), "+f"((c)[1]), "+f"((c)[2]), "+f"((c)[3]) \
                 : "r"((a)[0]), "r"((a)[1]), "r"((a)[2]), "r"((a)[3]), "r"(b0), "r"(b1))

// ================= CSR build (per call, deterministic input) =================
__global__ void zero_cnt_kernel() {
    int i = blockIdx.x * blockDim.x + threadIdx.x;
    if (i < NN) g_cnt[i] = 0;
}
__global__ void hist_kernel(const int* __restrict__ ei) {
    int e = blockIdx.x * blockDim.x + threadIdx.x;
    if (e < EE) atomicAdd(&g_cnt[ei[EE + e]], 1);
}

// ---- hierarchical scan ----
__global__ void __launch_bounds__(256) scan_local() {
    __shared__ int s_w[8];
    int tid = threadIdx.x, lane = tid & 31, wid = tid >> 5;
    int i = blockIdx.x * 256 + tid;
    int v = (i < NN) ? g_cnt[i] : 0;
    int x = v;
#pragma unroll
    for (int d = 1; d < 32; d <<= 1) {
        int t = __shfl_up_sync(0xffffffffu, x, d);
        if (lane >= d) x += t;
    }
    if (lane == 31) s_w[wid] = x;
    __syncthreads();
    if (wid == 0 && lane < 8) {
        int y = s_w[lane];
#pragma unroll
        for (int d = 1; d < 8; d <<= 1) {
            int t = __shfl_up_sync(0xffu, y, d);
            if (lane >= d) y += t;
        }
        s_w[lane] = y;
    }
    __syncthreads();
    int excl = (wid > 0 ? s_w[wid - 1] : 0) + x - v;
    if (i < NN) g_indptr[i] = excl;
    if (tid == 255) g_bsum[blockIdx.x] = s_w[7];
}

__global__ void __launch_bounds__(512) scan_bsums(int nblocks) {
    __shared__ int s_w[16];
    int tid = threadIdx.x, lane = tid & 31, wid = tid >> 5;
    int v = (tid < nblocks) ? g_bsum[tid] : 0;
    int x = v;
#pragma unroll
    for (int d = 1; d < 32; d <<= 1) {
        int t = __shfl_up_sync(0xffffffffu, x, d);
        if (lane >= d) x += t;
    }
    if (lane == 31) s_w[wid] = x;
    __syncthreads();
    if (wid == 0 && lane < 16) {
        int y = s_w[lane];
#pragma unroll
        for (int d = 1; d < 16; d <<= 1) {
            int t = __shfl_up_sync(0xffffu, y, d);
            if (lane >= d) y += t;
        }
        s_w[lane] = y;
    }
    __syncthreads();
    int excl = (wid > 0 ? s_w[wid - 1] : 0) + x - v;
    if (tid < nblocks) g_boff[tid] = excl;
}

__global__ void __launch_bounds__(256) scan_add() {
    int i = blockIdx.x * 256 + threadIdx.x;
    if (i < NN) {
        int val = g_indptr[i] + g_boff[blockIdx.x];
        g_indptr[i] = val;
        g_cursor[i] = val;
    }
    if (i == 0) g_indptr[NN] = EE;
}

__global__ void scatter_kernel(const int* __restrict__ ei) {
    int e = blockIdx.x * blockDim.x + threadIdx.x;
    if (e < EE) {
        int d = ei[EE + e];
        int pos = atomicAdd(&g_cursor[d], 1);
        g_col[pos] = ei[e];
    }
}

// ============ W prep: transpose + bf16 hi/lo split (both layers) ============
__global__ void prep_w(const float* __restrict__ Wq1, const float* __restrict__ Wk1,
                       const float* __restrict__ Wv1, const float* __restrict__ Ws1,
                       const float* __restrict__ Wq2, const float* __restrict__ Wk2,
                       const float* __restrict__ Wv2, const float* __restrict__ Ws2,
                       __nv_bfloat16* __restrict__ dst0) {
    int b = blockIdx.x;           // 0..25
    int layer = b / 13, c = b % 13;
    const float* Wq = layer ? Wq2 : Wq1;
    const float* Wk = layer ? Wk2 : Wk1;
    const float* Wv = layer ? Wv2 : Wv1;
    const float* Ws = layer ? Ws2 : Ws1;
    __nv_bfloat16* dst = dst0 + (size_t)layer * 13 * 8192;
    for (int i = threadIdx.x; i < 4096; i += 256) {
        int n = i >> 6, k = i & 63;
        float w;
        if (c < 4)       w = Wq[k * 256 + c * 64 + n];
        else if (c < 8)  w = Wk[k * 256 + (c - 4) * 64 + n];
        else if (c < 12) w = Wv[k * 256 + (c - 8) * 64 + n];
        else             w = Ws[k * 64 + n];
        __nv_bfloat16 hi = __float2bfloat16(w);
        float lo = w - __bfloat162float(hi);
        dst[c * 8192 + i]        = hi;
        dst[c * 8192 + 4096 + i] = __float2bfloat16(lo);
    }
}

// ============ mma.sync GEMM: 128 rows x 832 cols ============
// chunks 0-11 (q,k,v): pure bf16 single-term MMA (outputs stored bf16 anyway;
//   measured evidence: alpha-path noise irrelevant, v noise budget allows it)
// chunk 12 (skip): bf16x3 split, fp32-accurate
#define SM_BIAS 0
#define SM_AHI  3584
#define SM_ALO  22016
#define SM_BHI  40448
#define SM_BLO  49664
#define SM_STG  58880
#define SM_TOT  93696
#define LDA 72
#define LDB 72
#define STG 68

__global__ void __launch_bounds__(128) tc_gemm(
    const float* __restrict__ Xext, int useGh,
    const float* __restrict__ bq, const float* __restrict__ bk,
    const float* __restrict__ bv, const float* __restrict__ bs,
    const __nv_bfloat16* __restrict__ wb, int nrows)
{
    extern __shared__ char smem[];
    uint32_t sb = smem_u32(smem);
    const float* X = useGh ? g_h : Xext;
    int tid = threadIdx.x, w = tid >> 5, l = tid & 31;
    int row0 = blockIdx.x * 128;
    float* biasSm = reinterpret_cast<float*>(smem + SM_BIAS);
    float* stage  = reinterpret_cast<float*>(smem + SM_STG);

    for (int i = tid; i < 832; i += 128) {
        int c = i >> 6, j = i & 63;
        float b;
        if (c < 4)       b = bq[i];
        else if (c < 8)  b = bk[i - 256];
        else if (c < 12) b = bv[i - 512];
        else             b = bs[j];
        biasSm[i] = b;
    }

#pragma unroll
    for (int j = 0; j < 16; j++) {
        int idx = tid + j * 128;
        int r = idx >> 4, c4 = idx & 15;
        int gr = row0 + r;
        float4 xv = make_float4(0.f, 0.f, 0.f, 0.f);
        if (gr < nrows)
            xv = *reinterpret_cast<const float4*>(X + (size_t)gr * 64 + c4 * 4);
        __nv_bfloat16 h0 = __float2bfloat16(xv.x);
        __nv_bfloat16 h1 = __float2bfloat16(xv.y);
        __nv_bfloat16 h2 = __float2bfloat16(xv.z);
        __nv_bfloat16 h3 = __float2bfloat16(xv.w);
        __nv_bfloat162 hh0; hh0.x = h0; hh0.y = h1;
        __nv_bfloat162 hh1; hh1.x = h2; hh1.y = h3;
        __nv_bfloat162 ll0 = __floats2bfloat162_rn(xv.x - __bfloat162float(h0),
                                                   xv.y - __bfloat162float(h1));
        __nv_bfloat162 ll1 = __floats2bfloat162_rn(xv.z - __bfloat162float(h2),
                                                   xv.w - __bfloat162float(h3));
        uint2 uh, ul;
        uh.x = *reinterpret_cast<unsigned*>(&hh0);
        uh.y = *reinterpret_cast<unsigned*>(&hh1);
        ul.x = *reinterpret_cast<unsigned*>(&ll0);
        ul.y = *reinterpret_cast<unsigned*>(&ll1);
        size_t boff = (size_t)(r * LDA + c4 * 4) * 2;
        *reinterpret_cast<uint2*>(smem + SM_AHI + boff) = uh;
        *reinterpret_cast<uint2*>(smem + SM_ALO + boff) = ul;
    }

    int arow = w * 32 + (l & 15);
    int acol = (l >> 4) * 8;
    int bn   = (l & 7) + ((l >> 4) << 3);
    int bk8  = (l & 8);

    // ---- register prefetch of B-hi of chunk 0 (4 x uint4/thread = 8KB) ----
    uint4 pre[4];
#pragma unroll
    for (int j = 0; j < 4; j++)
        pre[j] = reinterpret_cast<const uint4*>(wb)[tid + j * 128];

    for (int c = 0; c < 13; c++) {
        // ---- publish B-hi chunk into smem [64][LDB] ----
#pragma unroll
        for (int j = 0; j < 4; j++) {
            int i = tid + j * 128;       // 0..511
            int n = i >> 3, k8 = i & 7;
            char* p = smem + SM_BHI + n * (LDB * 2) + k8 * 16;
            *reinterpret_cast<uint2*>(p)     = make_uint2(pre[j].x, pre[j].y);
            *reinterpret_cast<uint2*>(p + 8) = make_uint2(pre[j].z, pre[j].w);
        }
        // ---- skip chunk: also stage B-lo (one-time latency, fine) ----
        if (c == 12) {
#pragma unroll
            for (int j = 0; j < 4; j++) {
                int i = tid + j * 128;
                uint4 v = reinterpret_cast<const uint4*>(wb + 12 * 8192 + 4096)[i];
                int n = i >> 3, k8 = i & 7;
                char* p = smem + SM_BLO + n * (LDB * 2) + k8 * 16;
                *reinterpret_cast<uint2*>(p)     = make_uint2(v.x, v.y);
                *reinterpret_cast<uint2*>(p + 8) = make_uint2(v.z, v.w);
            }
        }
        __syncthreads();

        // ---- issue LDGs for next chunk's hi (overlap with MMA) ----
        if (c + 1 < 13) {
#pragma unroll
            for (int j = 0; j < 4; j++)
                pre[j] = reinterpret_cast<const uint4*>(wb + (size_t)(c + 1) * 8192)[tid + j * 128];
        }

        float acc[2][8][4];
#pragma unroll
        for (int mt = 0; mt < 2; mt++)
#pragma unroll
            for (int nt = 0; nt < 8; nt++)
#pragma unroll
                for (int q = 0; q < 4; q++) acc[mt][nt][q] = 0.f;

        if (c < 12) {
            // ---- light path: pure bf16, 2 MMAs per (mt,np) ----
#pragma unroll
            for (int kt = 0; kt < 4; kt++) {
                uint32_t ah[2][4];
#pragma unroll
                for (int mt = 0; mt < 2; mt++) {
                    uint32_t off = (uint32_t)(((arow + mt * 16) * LDA + kt * 16 + acol) * 2);
                    LDMX4(ah[mt][0], ah[mt][1], ah[mt][2], ah[mt][3], sb + SM_AHI + off);
                }
                uint32_t bh[4][4];
#pragma unroll
                for (int np = 0; np < 4; np++) {
                    uint32_t off = (uint32_t)(((bn + np * 16) * LDB + kt * 16 + bk8) * 2);
                    LDMX4(bh[np][0], bh[np][1], bh[np][2], bh[np][3], sb + SM_BHI + off);
                }
#pragma unroll
                for (int mt = 0; mt < 2; mt++) {
#pragma unroll
                    for (int np = 0; np < 4; np++) {
                        MMA16816(acc[mt][np * 2],     ah[mt], bh[np][0], bh[np][1]);
                        MMA16816(acc[mt][np * 2 + 1], ah[mt], bh[np][2], bh[np][3]);
                    }
                }
            }
        } else {
            // ---- skip chunk: full bf16x3 split (fp32-accurate) ----
#pragma unroll
            for (int kt = 0; kt < 4; kt++) {
                uint32_t ah[2][4], al[2][4];
#pragma unroll
                for (int mt = 0; mt < 2; mt++) {
                    uint32_t off = (uint32_t)(((arow + mt * 16) * LDA + kt * 16 + acol) * 2);
                    LDMX4(ah[mt][0], ah[mt][1], ah[mt][2], ah[mt][3], sb + SM_AHI + off);
                    LDMX4(al[mt][0], al[mt][1], al[mt][2], al[mt][3], sb + SM_ALO + off);
                }
                uint32_t bh[4][4], bl[4][4];
#pragma unroll
                for (int np = 0; np < 4; np++) {
                    uint32_t off = (uint32_t)(((bn + np * 16) * LDB + kt * 16 + bk8) * 2);
                    LDMX4(bh[np][0], bh[np][1], bh[np][2], bh[np][3], sb + SM_BHI + off);
                    LDMX4(bl[np][0], bl[np][1], bl[np][2], bl[np][3], sb + SM_BLO + off);
                }
#pragma unroll
                for (int mt = 0; mt < 2; mt++) {
#pragma unroll
                    for (int np = 0; np < 4; np++) {
                        MMA16816(acc[mt][np * 2],     ah[mt], bh[np][0], bh[np][1]);
                        MMA16816(acc[mt][np * 2],     ah[mt], bl[np][0], bl[np][1]);
                        MMA16816(acc[mt][np * 2],     al[mt], bh[np][0], bh[np][1]);
                        MMA16816(acc[mt][np * 2 + 1], ah[mt], bh[np][2], bh[np][3]);
                        MMA16816(acc[mt][np * 2 + 1], ah[mt], bl[np][2], bl[np][3]);
                        MMA16816(acc[mt][np * 2 + 1], al[mt], bh[np][2], bh[np][3]);
                    }
                }
            }
        }

        int rs = w * 32 + (l >> 2);
        int cs = (l & 3) * 2;
#pragma unroll
        for (int mt = 0; mt < 2; mt++) {
#pragma unroll
            for (int nt = 0; nt < 8; nt++) {
                int col = nt * 8 + cs;
                *reinterpret_cast<float2*>(stage + (rs + mt * 16) * STG + col) =
                    make_float2(acc[mt][nt][0], acc[mt][nt][1]);
                *reinterpret_cast<float2*>(stage + (rs + mt * 16 + 8) * STG + col) =
                    make_float2(acc[mt][nt][2], acc[mt][nt][3]);
            }
        }
        __syncthreads();

#pragma unroll
        for (int j = 0; j < 16; j++) {
            int idx = tid + j * 128;
            int r = idx >> 4, c4 = idx & 15;
            int gr = row0 + r;
            if (gr >= nrows) continue;
            float4 o = *reinterpret_cast<const float4*>(stage + r * STG + c4 * 4);
            const float4 bb = *reinterpret_cast<const float4*>(biasSm + c * 64 + c4 * 4);
            o.x += bb.x; o.y += bb.y; o.z += bb.z; o.w += bb.w;
            if (c < 12) {
                __nv_bfloat162 p0 = __floats2bfloat162_rn(o.x, o.y);
                __nv_bfloat162 p1 = __floats2bfloat162_rn(o.z, o.w);
                uint2 u;
                u.x = *reinterpret_cast<unsigned*>(&p0);
                u.y = *reinterpret_cast<unsigned*>(&p1);
                if (c < 4) {
                    *reinterpret_cast<uint2*>(g_qb + (size_t)gr * 256 + c * 64 + c4 * 4) = u;
                } else {
                    int col0 = (c < 8) ? (c - 4) * 64 : (c - 8) * 64 + 256;
                    *reinterpret_cast<uint2*>(g_kv + (size_t)gr * 512 + col0 + c4 * 4) = u;
                }
            } else {
                *reinterpret_cast<float4*>(g_skip + (size_t)gr * 64 + c4 * 4) = o;
            }
        }
        __syncthreads();
    }
}

// ====== fused attention + epilogue: one warp per destination node ======
__device__ __forceinline__ float2 bf2f(unsigned u) {
    __nv_bfloat162 t = *reinterpret_cast<__nv_bfloat162*>(&u);
    return __bfloat1622float2(t);
}

__global__ void __launch_bounds__(256) attn_kernel(float* __restrict__ out_ext,
                                                   int to_gh, int relu) {
    int n = (blockIdx.x * blockDim.x + threadIdx.x) >> 5;
    if (n >= NN) return;
    int lane = threadIdx.x & 31;
    int h = lane >> 3, m = lane & 7;
    int koff = h * 8 + m;

    uint4 qr = reinterpret_cast<const uint4*>(g_qb)[(size_t)n * 32 + koff];
    float2 t0 = bf2f(qr.x), t1 = bf2f(qr.y), t2 = bf2f(qr.z), t3 = bf2f(qr.w);
    float4 q0 = make_float4(t0.x, t0.y, t1.x, t1.y);
    float4 q1 = make_float4(t2.x, t2.y, t3.x, t3.y);

    float acc[8] = {0.f, 0.f, 0.f, 0.f, 0.f, 0.f, 0.f, 0.f};
    float den = 0.f;

    const uint4* kvp = reinterpret_cast<const uint4*>(g_kv);

    int e0 = g_indptr[n], e1 = g_indptr[n + 1];
    int e = e0;

    for (; e + 2 <= e1; e += 2) {
        int sA = g_col[e], sB = g_col[e + 1];
        uint4 krA = kvp[(size_t)sA * 64 + koff];
        uint4 krB = kvp[(size_t)sB * 64 + koff];
        uint4 vrA = kvp[(size_t)sA * 64 + 32 + koff];
        uint4 vrB = kvp[(size_t)sB * 64 + 32 + koff];

        float2 a0 = bf2f(krA.x), a1 = bf2f(krA.y), a2 = bf2f(krA.z), a3 = bf2f(krA.w);
        float2 c0 = bf2f(krB.x), c1 = bf2f(krB.y), c2 = bf2f(krB.z), c3 = bf2f(krB.w);
        float pA = q0.x * a0.x + q0.y * a0.y + q0.z * a1.x + q0.w * a1.y
                 + q1.x * a2.x + q1.y * a2.y + q1.z * a3.x + q1.w * a3.y;
        float pB = q0.x * c0.x + q0.y * c0.y + q0.z * c1.x + q0.w * c1.y
                 + q1.x * c2.x + q1.y * c2.y + q1.z * c3.x + q1.w * c3.y;
        pA += __shfl_xor_sync(0xffffffffu, pA, 1);
        pB += __shfl_xor_sync(0xffffffffu, pB, 1);
        pA += __shfl_xor_sync(0xffffffffu, pA, 2);
        pB += __shfl_xor_sync(0xffffffffu, pB, 2);
        pA += __shfl_xor_sync(0xffffffffu, pA, 4);
        pB += __shfl_xor_sync(0xffffffffu, pB, 4);
        float exA = __expf(pA * 0.125f);
        float exB = __expf(pB * 0.125f);

        float2 vA0 = bf2f(vrA.x), vA1 = bf2f(vrA.y), vA2 = bf2f(vrA.z), vA3 = bf2f(vrA.w);
        float2 vB0 = bf2f(vrB.x), vB1 = bf2f(vrB.y), vB2 = bf2f(vrB.z), vB3 = bf2f(vrB.w);
        acc[0] += exA * vA0.x + exB * vB0.x;
        acc[1] += exA * vA0.y + exB * vB0.y;
        acc[2] += exA * vA1.x + exB * vB1.x;
        acc[3] += exA * vA1.y + exB * vB1.y;
        acc[4] += exA * vA2.x + exB * vB2.x;
        acc[5] += exA * vA2.y + exB * vB2.y;
        acc[6] += exA * vA3.x + exB * vB3.x;
        acc[7] += exA * vA3.y + exB * vB3.y;
        den += exA + exB;
    }
    if (e < e1) {
        int s = g_col[e];
        uint4 kr = kvp[(size_t)s * 64 + koff];
        uint4 vr = kvp[(size_t)s * 64 + 32 + koff];
        float2 k0 = bf2f(kr.x), k1 = bf2f(kr.y), k2 = bf2f(kr.z), k3 = bf2f(kr.w);
        float p = q0.x * k0.x + q0.y * k0.y + q0.z * k1.x + q0.w * k1.y
                + q1.x * k2.x + q1.y * k2.y + q1.z * k3.x + q1.w * k3.y;
        p += __shfl_xor_sync(0xffffffffu, p, 1);
        p += __shfl_xor_sync(0xffffffffu, p, 2);
        p += __shfl_xor_sync(0xffffffffu, p, 4);
        float ex = __expf(p * 0.125f);
        float2 v0 = bf2f(vr.x), v1 = bf2f(vr.y), v2 = bf2f(vr.z), v3 = bf2f(vr.w);
        acc[0] += ex * v0.x; acc[1] += ex * v0.y;
        acc[2] += ex * v1.x; acc[3] += ex * v1.y;
        acc[4] += ex * v2.x; acc[5] += ex * v2.y;
        acc[6] += ex * v3.x; acc[7] += ex * v3.y;
        den += ex;
    }

    float inv = 1.0f / (den + 1e-16f);
#pragma unroll
    for (int j = 0; j < 8; j++) {
        float r = acc[j] * inv;
        r += __shfl_xor_sync(0xffffffffu, r, 8);
        r += __shfl_xor_sync(0xffffffffu, r, 16);
        acc[j] = r * 0.25f;
    }

    if (h == 0) {
        float* out = to_gh ? g_h : out_ext;
        size_t ob = (size_t)n * DD + m * 8;
        float4 s0 = *reinterpret_cast<const float4*>(g_skip + ob);
        float4 s1 = *reinterpret_cast<const float4*>(g_skip + ob + 4);
        float4 o0, o1;
        o0.x = acc[0] + s0.x; o0.y = acc[1] + s0.y;
        o0.z = acc[2] + s0.z; o0.w = acc[3] + s0.w;
        o1.x = acc[4] + s1.x; o1.y = acc[5] + s1.y;
        o1.z = acc[6] + s1.z; o1.w = acc[7] + s1.w;
        if (relu) {
            o0.x = fmaxf(o0.x, 0.f); o0.y = fmaxf(o0.y, 0.f);
            o0.z = fmaxf(o0.z, 0.f); o0.w = fmaxf(o0.w, 0.f);
            o1.x = fmaxf(o1.x, 0.f); o1.y = fmaxf(o1.y, 0.f);
            o1.z = fmaxf(o1.z, 0.f); o1.w = fmaxf(o1.w, 0.f);
        }
        *reinterpret_cast<float4*>(out + ob)     = o0;
        *reinterpret_cast<float4*>(out + ob + 4) = o1;
    }
}

extern "C" void kernel_launch(void* const* d_in, const int* in_sizes, int n_in,
                              void* d_out, int out_size) {
    const float* x   = (const float*)d_in[0];
    const int*   ei  = (const int*)d_in[1];
    const float* Wq1 = (const float*)d_in[2];
    const float* bq1 = (const float*)d_in[3];
    const float* Wk1 = (const float*)d_in[4];
    const float* bk1 = (const float*)d_in[5];
    const float* Wv1 = (const float*)d_in[6];
    const float* bv1 = (const float*)d_in[7];
    const float* Ws1 = (const float*)d_in[8];
    const float* bs1 = (const float*)d_in[9];
    const float* Wq2 = (const float*)d_in[10];
    const float* bq2 = (const float*)d_in[11];
    const float* Wk2 = (const float*)d_in[12];
    const float* bk2 = (const float*)d_in[13];
    const float* Wv2 = (const float*)d_in[14];
    const float* bv2 = (const float*)d_in[15];
    const float* Ws2 = (const float*)d_in[16];
    const float* bs2 = (const float*)d_in[17];
    float* out = (float*)d_out;

    static cudaStream_t s_side = nullptr;
    static cudaEvent_t ev_root = nullptr, ev_side = nullptr;
    if (!s_side) {
        cudaStreamCreateWithFlags(&s_side, cudaStreamNonBlocking);
        cudaEventCreateWithFlags(&ev_root, cudaEventDisableTiming);
        cudaEventCreateWithFlags(&ev_side, cudaEventDisableTiming);
        cudaFuncSetAttribute(tc_gemm, cudaFuncAttributeMaxDynamicSharedMemorySize, SM_TOT);
    }

    __nv_bfloat16* wb_dev = nullptr;
    cudaGetSymbolAddress((void**)&wb_dev, g_wb);

    int scan_blocks = (NN + 255) / 256;
    int gemm_blocks = (NN + 127) / 128;
    int attn_blocks = (NN * 32 + 255) / 256;

    // ---- fork: prep_w + gemm1 (side stream) || CSR build (main stream) ----
    cudaEventRecord(ev_root, 0);
    cudaStreamWaitEvent(s_side, ev_root, 0);

    prep_w<<<26, 256, 0, s_side>>>(Wq1, Wk1, Wv1, Ws1, Wq2, Wk2, Wv2, Ws2, wb_dev);
    tc_gemm<<<gemm_blocks, 128, SM_TOT, s_side>>>(x, 0, bq1, bk1, bv1, bs1, wb_dev, NN);
    cudaEventRecord(ev_side, s_side);

    zero_cnt_kernel<<<(NN + 255) / 256, 256>>>();
    hist_kernel<<<(EE + 255) / 256, 256>>>(ei);
    scan_local<<<scan_blocks, 256>>>();
    scan_bsums<<<1, 512>>>(scan_blocks);
    scan_add<<<scan_blocks, 256>>>();
    scatter_kernel<<<(EE + 255) / 256, 256>>>(ei);

    cudaStreamWaitEvent(0, ev_side, 0);

    attn_kernel<<<attn_blocks, 256>>>(nullptr, /*to_gh=*/1, /*relu=*/1);
    tc_gemm<<<gemm_blocks, 128, SM_TOT>>>(nullptr, 1, bq2, bk2, bv2, bs2, wb_dev + 13 * 8192, NN);
    attn_kernel<<<attn_blocks, 256>>>(out, /*to_gh=*/0, /*relu=*/0);
}

// round 15
// speedup vs baseline: 1.2289x; 1.1034x over previous
#include <cuda_runtime.h>
#include <cuda_bf16.h>
#include <cstdint>

#define NN 100000
#define EE 800000
#define DD 64
#define HH 4
#define HC 256

// ---- scratch (static device globals: allocation-free) ----
__device__ __nv_bfloat16 g_qb[(size_t)NN * HC];        // bf16 Q  [N][256]
__device__ __nv_bfloat16 g_kv[(size_t)NN * 512];       // bf16 K||V per node: [N][512]
__device__ float g_skip[(size_t)NN * DD];
__device__ float g_h[(size_t)NN * DD];
__device__ int   g_cnt[NN];
__device__ int   g_indptr[NN + 1];
__device__ int   g_cursor[NN];
__device__ int   g_col[EE];
__device__ int   g_bsum[512];
__device__ int   g_boff[512];
// W in bf16 hi/lo, transposed: [layer][chunk 13][part 2][n 64][k 64]
__device__ __nv_bfloat16 g_wb[2 * 13 * 2 * 64 * 64];

__device__ __forceinline__ uint32_t smem_u32(const void* p) {
    uint32_t a;
    asm("{ .reg .u64 t; cvta.to.shared.u64 t, %1; cvt.u32.u64 %0, t; }" : "=r"(a) : "l"(p));
    return a;
}

#define LDMX4(d0, d1, d2, d3, a) \
    asm volatile("ldmatrix.sync.aligned.m8n8.x4.shared.b16 {%0,%1,%2,%3}, [%4];" \
                 : "=r"(d0), "=r"(d1), "=r"(d2), "=r"(d3) : "r"(a))

#define MMA16816(c, a, b0, b1) \
    asm volatile("mma.sync.aligned.m16n8k16.row.col.f32.bf16.bf16.f32 " \
                 "{%0,%1,%2,%3}, {%4,%5,%6,%7}, {%8,%9}, {%0,%1,%2,%3};" \
                 : "+f"((c)[0]), "+f"((c)[1]), "+f"((c)[2]), "+f"((c)[3]) \
                 : "r"((a)[0]), "r"((a)[1]), "r"((a)[2]), "r"((a)[3]), "r"(b0), "r"(b1))

// ================= CSR build (per call, deterministic input) =================
__global__ void zero_cnt_kernel() {
    int i = blockIdx.x * blockDim.x + threadIdx.x;
    if (i < NN) g_cnt[i] = 0;
}
__global__ void hist_kernel(const int* __restrict__ ei) {
    int e = blockIdx.x * blockDim.x + threadIdx.x;
    if (e < EE) atomicAdd(&g_cnt[ei[EE + e]], 1);
}

// ---- hierarchical scan ----
__global__ void __launch_bounds__(256) scan_local() {
    __shared__ int s_w[8];
    int tid = threadIdx.x, lane = tid & 31, wid = tid >> 5;
    int i = blockIdx.x * 256 + tid;
    int v = (i < NN) ? g_cnt[i] : 0;
    int x = v;
#pragma unroll
    for (int d = 1; d < 32; d <<= 1) {
        int t = __shfl_up_sync(0xffffffffu, x, d);
        if (lane >= d) x += t;
    }
    if (lane == 31) s_w[wid] = x;
    __syncthreads();
    if (wid == 0 && lane < 8) {
        int y = s_w[lane];
#pragma unroll
        for (int d = 1; d < 8; d <<= 1) {
            int t = __shfl_up_sync(0xffu, y, d);
            if (lane >= d) y += t;
        }
        s_w[lane] = y;
    }
    __syncthreads();
    int excl = (wid > 0 ? s_w[wid - 1] : 0) + x - v;
    if (i < NN) g_indptr[i] = excl;
    if (tid == 255) g_bsum[blockIdx.x] = s_w[7];
}

__global__ void __launch_bounds__(512) scan_bsums(int nblocks) {
    __shared__ int s_w[16];
    int tid = threadIdx.x, lane = tid & 31, wid = tid >> 5;
    int v = (tid < nblocks) ? g_bsum[tid] : 0;
    int x = v;
#pragma unroll
    for (int d = 1; d < 32; d <<= 1) {
        int t = __shfl_up_sync(0xffffffffu, x, d);
        if (lane >= d) x += t;
    }
    if (lane == 31) s_w[wid] = x;
    __syncthreads();
    if (wid == 0 && lane < 16) {
        int y = s_w[lane];
#pragma unroll
        for (int d = 1; d < 16; d <<= 1) {
            int t = __shfl_up_sync(0xffffu, y, d);
            if (lane >= d) y += t;
        }
        s_w[lane] = y;
    }
    __syncthreads();
    int excl = (wid > 0 ? s_w[wid - 1] : 0) + x - v;
    if (tid < nblocks) g_boff[tid] = excl;
}

__global__ void __launch_bounds__(256) scan_add() {
    int i = blockIdx.x * 256 + threadIdx.x;
    if (i < NN) {
        int val = g_indptr[i] + g_boff[blockIdx.x];
        g_indptr[i] = val;
        g_cursor[i] = val;
    }
    if (i == 0) g_indptr[NN] = EE;
}

__global__ void scatter_kernel(const int* __restrict__ ei) {
    int e = blockIdx.x * blockDim.x + threadIdx.x;
    if (e < EE) {
        int d = ei[EE + e];
        int pos = atomicAdd(&g_cursor[d], 1);
        g_col[pos] = ei[e];
    }
}

// ============ W prep (one layer): transpose + bf16 hi/lo split ============
__global__ void prep_w(const float* __restrict__ Wq, const float* __restrict__ Wk,
                       const float* __restrict__ Wv, const float* __restrict__ Ws,
                       __nv_bfloat16* __restrict__ dst) {
    int c = blockIdx.x;           // 0..12
    for (int i = threadIdx.x; i < 4096; i += 256) {
        int n = i >> 6, k = i & 63;
        float w;
        if (c < 4)       w = Wq[k * 256 + c * 64 + n];
        else if (c < 8)  w = Wk[k * 256 + (c - 4) * 64 + n];
        else if (c < 12) w = Wv[k * 256 + (c - 8) * 64 + n];
        else             w = Ws[k * 64 + n];
        __nv_bfloat16 hi = __float2bfloat16(w);
        float lo = w - __bfloat162float(hi);
        dst[c * 8192 + i]        = hi;
        dst[c * 8192 + 4096 + i] = __float2bfloat16(lo);
    }
}

// ============ mma.sync GEMM: 128 rows x 832 cols ============
// chunks 0-7 (q,k): pure bf16 single-term (alpha-path noise empirically irrelevant)
// chunks 8-11 (v): 2-term split Ahi*Bhi + Alo*Bhi (A-lo already in smem, free traffic)
// chunk 12 (skip): bf16x3 split, fp32-accurate
#define SM_BIAS 0
#define SM_AHI  3584
#define SM_ALO  22016
#define SM_BHI  40448
#define SM_BLO  49664
#define SM_STG  58880
#define SM_TOT  93696
#define LDA 72
#define LDB 72
#define STG 68
#define STGU 36    // uint stride for bf16 staging

__global__ void __launch_bounds__(128) tc_gemm(
    const float* __restrict__ Xext, int useGh,
    const float* __restrict__ bq, const float* __restrict__ bk,
    const float* __restrict__ bv, const float* __restrict__ bs,
    const __nv_bfloat16* __restrict__ wb, int nrows)
{
    extern __shared__ char smem[];
    uint32_t sb = smem_u32(smem);
    const float* X = useGh ? g_h : Xext;
    int tid = threadIdx.x, w = tid >> 5, l = tid & 31;
    int row0 = blockIdx.x * 128;
    float* biasSm = reinterpret_cast<float*>(smem + SM_BIAS);
    float* stage  = reinterpret_cast<float*>(smem + SM_STG);
    uint32_t* stu = reinterpret_cast<uint32_t*>(smem + SM_STG);

    for (int i = tid; i < 832; i += 128) {
        int c = i >> 6, j = i & 63;
        float b;
        if (c < 4)       b = bq[i];
        else if (c < 8)  b = bk[i - 256];
        else if (c < 12) b = bv[i - 512];
        else             b = bs[j];
        biasSm[i] = b;
    }

#pragma unroll
    for (int j = 0; j < 16; j++) {
        int idx = tid + j * 128;
        int r = idx >> 4, c4 = idx & 15;
        int gr = row0 + r;
        float4 xv = make_float4(0.f, 0.f, 0.f, 0.f);
        if (gr < nrows)
            xv = *reinterpret_cast<const float4*>(X + (size_t)gr * 64 + c4 * 4);
        __nv_bfloat16 h0 = __float2bfloat16(xv.x);
        __nv_bfloat16 h1 = __float2bfloat16(xv.y);
        __nv_bfloat16 h2 = __float2bfloat16(xv.z);
        __nv_bfloat16 h3 = __float2bfloat16(xv.w);
        __nv_bfloat162 hh0; hh0.x = h0; hh0.y = h1;
        __nv_bfloat162 hh1; hh1.x = h2; hh1.y = h3;
        __nv_bfloat162 ll0 = __floats2bfloat162_rn(xv.x - __bfloat162float(h0),
                                                   xv.y - __bfloat162float(h1));
        __nv_bfloat162 ll1 = __floats2bfloat162_rn(xv.z - __bfloat162float(h2),
                                                   xv.w - __bfloat162float(h3));
        uint2 uh, ul;
        uh.x = *reinterpret_cast<unsigned*>(&hh0);
        uh.y = *reinterpret_cast<unsigned*>(&hh1);
        ul.x = *reinterpret_cast<unsigned*>(&ll0);
        ul.y = *reinterpret_cast<unsigned*>(&ll1);
        size_t boff = (size_t)(r * LDA + c4 * 4) * 2;
        *reinterpret_cast<uint2*>(smem + SM_AHI + boff) = uh;
        *reinterpret_cast<uint2*>(smem + SM_ALO + boff) = ul;
    }

    int arow = w * 32 + (l & 15);
    int acol = (l >> 4) * 8;
    int bn   = (l & 7) + ((l >> 4) << 3);
    int bk8  = (l & 8);

    // ---- register prefetch of B-hi of chunk 0 (4 x uint4/thread = 8KB) ----
    uint4 pre[4];
#pragma unroll
    for (int j = 0; j < 4; j++)
        pre[j] = reinterpret_cast<const uint4*>(wb)[tid + j * 128];

    for (int c = 0; c < 13; c++) {
        // ---- publish B-hi chunk into smem [64][LDB] ----
#pragma unroll
        for (int j = 0; j < 4; j++) {
            int i = tid + j * 128;       // 0..511
            int n = i >> 3, k8 = i & 7;
            char* p = smem + SM_BHI + n * (LDB * 2) + k8 * 16;
            *reinterpret_cast<uint2*>(p)     = make_uint2(pre[j].x, pre[j].y);
            *reinterpret_cast<uint2*>(p + 8) = make_uint2(pre[j].z, pre[j].w);
        }
        if (c == 12) {   // skip chunk: also stage B-lo
#pragma unroll
            for (int j = 0; j < 4; j++) {
                int i = tid + j * 128;
                uint4 v = reinterpret_cast<const uint4*>(wb + 12 * 8192 + 4096)[i];
                int n = i >> 3, k8 = i & 7;
                char* p = smem + SM_BLO + n * (LDB * 2) + k8 * 16;
                *reinterpret_cast<uint2*>(p)     = make_uint2(v.x, v.y);
                *reinterpret_cast<uint2*>(p + 8) = make_uint2(v.z, v.w);
            }
        }
        __syncthreads();

        if (c + 1 < 13) {
#pragma unroll
            for (int j = 0; j < 4; j++)
                pre[j] = reinterpret_cast<const uint4*>(wb + (size_t)(c + 1) * 8192)[tid + j * 128];
        }

        float acc[2][8][4];
#pragma unroll
        for (int mt = 0; mt < 2; mt++)
#pragma unroll
            for (int nt = 0; nt < 8; nt++)
#pragma unroll
                for (int q = 0; q < 4; q++) acc[mt][nt][q] = 0.f;

        if (c < 8) {
            // ---- q,k: pure bf16 single-term ----
#pragma unroll
            for (int kt = 0; kt < 4; kt++) {
                uint32_t ah[2][4];
#pragma unroll
                for (int mt = 0; mt < 2; mt++) {
                    uint32_t off = (uint32_t)(((arow + mt * 16) * LDA + kt * 16 + acol) * 2);
                    LDMX4(ah[mt][0], ah[mt][1], ah[mt][2], ah[mt][3], sb + SM_AHI + off);
                }
                uint32_t bh[4][4];
#pragma unroll
                for (int np = 0; np < 4; np++) {
                    uint32_t off = (uint32_t)(((bn + np * 16) * LDB + kt * 16 + bk8) * 2);
                    LDMX4(bh[np][0], bh[np][1], bh[np][2], bh[np][3], sb + SM_BHI + off);
                }
#pragma unroll
                for (int mt = 0; mt < 2; mt++) {
#pragma unroll
                    for (int np = 0; np < 4; np++) {
                        MMA16816(acc[mt][np * 2],     ah[mt], bh[np][0], bh[np][1]);
                        MMA16816(acc[mt][np * 2 + 1], ah[mt], bh[np][2], bh[np][3]);
                    }
                }
            }
        } else if (c < 12) {
            // ---- v: 2-term split (Ahi + Alo) * Bhi ----
#pragma unroll
            for (int kt = 0; kt < 4; kt++) {
                uint32_t ah[2][4], al[2][4];
#pragma unroll
                for (int mt = 0; mt < 2; mt++) {
                    uint32_t off = (uint32_t)(((arow + mt * 16) * LDA + kt * 16 + acol) * 2);
                    LDMX4(ah[mt][0], ah[mt][1], ah[mt][2], ah[mt][3], sb + SM_AHI + off);
                    LDMX4(al[mt][0], al[mt][1], al[mt][2], al[mt][3], sb + SM_ALO + off);
                }
                uint32_t bh[4][4];
#pragma unroll
                for (int np = 0; np < 4; np++) {
                    uint32_t off = (uint32_t)(((bn + np * 16) * LDB + kt * 16 + bk8) * 2);
                    LDMX4(bh[np][0], bh[np][1], bh[np][2], bh[np][3], sb + SM_BHI + off);
                }
#pragma unroll
                for (int mt = 0; mt < 2; mt++) {
#pragma unroll
                    for (int np = 0; np < 4; np++) {
                        MMA16816(acc[mt][np * 2],     ah[mt], bh[np][0], bh[np][1]);
                        MMA16816(acc[mt][np * 2],     al[mt], bh[np][0], bh[np][1]);
                        MMA16816(acc[mt][np * 2 + 1], ah[mt], bh[np][2], bh[np][3]);
                        MMA16816(acc[mt][np * 2 + 1], al[mt], bh[np][2], bh[np][3]);
                    }
                }
            }
        } else {
            // ---- skip: full bf16x3 split (fp32-accurate) ----
#pragma unroll
            for (int kt = 0; kt < 4; kt++) {
                uint32_t ah[2][4], al[2][4];
#pragma unroll
                for (int mt = 0; mt < 2; mt++) {
                    uint32_t off = (uint32_t)(((arow + mt * 16) * LDA + kt * 16 + acol) * 2);
                    LDMX4(ah[mt][0], ah[mt][1], ah[mt][2], ah[mt][3], sb + SM_AHI + off);
                    LDMX4(al[mt][0], al[mt][1], al[mt][2], al[mt][3], sb + SM_ALO + off);
                }
                uint32_t bh[4][4], bl[4][4];
#pragma unroll
                for (int np = 0; np < 4; np++) {
                    uint32_t off = (uint32_t)(((bn + np * 16) * LDB + kt * 16 + bk8) * 2);
                    LDMX4(bh[np][0], bh[np][1], bh[np][2], bh[np][3], sb + SM_BHI + off);
                    LDMX4(bl[np][0], bl[np][1], bl[np][2], bl[np][3], sb + SM_BLO + off);
                }
#pragma unroll
                for (int mt = 0; mt < 2; mt++) {
#pragma unroll
                    for (int np = 0; np < 4; np++) {
                        MMA16816(acc[mt][np * 2],     ah[mt], bh[np][0], bh[np][1]);
                        MMA16816(acc[mt][np * 2],     ah[mt], bl[np][0], bl[np][1]);
                        MMA16816(acc[mt][np * 2],     al[mt], bh[np][0], bh[np][1]);
                        MMA16816(acc[mt][np * 2 + 1], ah[mt], bh[np][2], bh[np][3]);
                        MMA16816(acc[mt][np * 2 + 1], ah[mt], bl[np][2], bl[np][3]);
                        MMA16816(acc[mt][np * 2 + 1], al[mt], bh[np][2], bh[np][3]);
                    }
                }
            }
        }

        if (c < 12) {
            // ---- bf16 staging: bias + pack during stage; stage uint[128][36] ----
            int rs = w * 32 + (l >> 2);
            int csh = (l & 3);
#pragma unroll
            for (int mt = 0; mt < 2; mt++) {
#pragma unroll
                for (int nt = 0; nt < 8; nt++) {
                    int colu = nt * 4 + csh;
                    int colc = colu * 2;
                    float b0 = biasSm[c * 64 + colc];
                    float b1 = biasSm[c * 64 + colc + 1];
                    __nv_bfloat162 p0 = __floats2bfloat162_rn(acc[mt][nt][0] + b0,
                                                              acc[mt][nt][1] + b1);
                    __nv_bfloat162 p1 = __floats2bfloat162_rn(acc[mt][nt][2] + b0,
                                                              acc[mt][nt][3] + b1);
                    stu[(rs + mt * 16) * STGU + colu]     = *reinterpret_cast<unsigned*>(&p0);
                    stu[(rs + mt * 16 + 8) * STGU + colu] = *reinterpret_cast<unsigned*>(&p1);
                }
            }
            __syncthreads();
            // ---- coalesced uint4 store: 128 rows x 8 uint4 ----
#pragma unroll
            for (int j = 0; j < 8; j++) {
                int idx = tid + j * 128;
                int r = idx >> 3, cu4 = idx & 7;
                int gr = row0 + r;
                if (gr >= nrows) continue;
                uint4 u = *reinterpret_cast<const uint4*>(&stu[r * STGU + cu4 * 4]);
                if (c < 4) {
                    *reinterpret_cast<uint4*>(g_qb + (size_t)gr * 256 + c * 64 + cu4 * 8) = u;
                } else {
                    int col0 = (c < 8) ? (c - 4) * 64 : (c - 8) * 64 + 256;
                    *reinterpret_cast<uint4*>(g_kv + (size_t)gr * 512 + col0 + cu4 * 8) = u;
                }
            }
            __syncthreads();
        } else {
            // ---- fp32 staging for skip chunk ----
            int rs = w * 32 + (l >> 2);
            int cs = (l & 3) * 2;
#pragma unroll
            for (int mt = 0; mt < 2; mt++) {
#pragma unroll
                for (int nt = 0; nt < 8; nt++) {
                    int col = nt * 8 + cs;
                    *reinterpret_cast<float2*>(stage + (rs + mt * 16) * STG + col) =
                        make_float2(acc[mt][nt][0], acc[mt][nt][1]);
                    *reinterpret_cast<float2*>(stage + (rs + mt * 16 + 8) * STG + col) =
                        make_float2(acc[mt][nt][2], acc[mt][nt][3]);
                }
            }
            __syncthreads();
#pragma unroll
            for (int j = 0; j < 16; j++) {
                int idx = tid + j * 128;
                int r = idx >> 4, c4 = idx & 15;
                int gr = row0 + r;
                if (gr >= nrows) continue;
                float4 o = *reinterpret_cast<const float4*>(stage + r * STG + c4 * 4);
                const float4 bb = *reinterpret_cast<const float4*>(biasSm + 12 * 64 + c4 * 4);
                o.x += bb.x; o.y += bb.y; o.z += bb.z; o.w += bb.w;
                *reinterpret_cast<float4*>(g_skip + (size_t)gr * 64 + c4 * 4) = o;
            }
            __syncthreads();
        }
    }
}

// ====== fused attention + epilogue: one warp per destination node ======
__device__ __forceinline__ float2 bf2f(unsigned u) {
    __nv_bfloat162 t = *reinterpret_cast<__nv_bfloat162*>(&u);
    return __bfloat1622float2(t);
}

__global__ void __launch_bounds__(256) attn_kernel(float* __restrict__ out_ext,
                                                   int to_gh, int relu) {
    int n = (blockIdx.x * blockDim.x + threadIdx.x) >> 5;
    if (n >= NN) return;
    int lane = threadIdx.x & 31;
    int h = lane >> 3, m = lane & 7;
    int koff = h * 8 + m;

    uint4 qr = reinterpret_cast<const uint4*>(g_qb)[(size_t)n * 32 + koff];
    float2 t0 = bf2f(qr.x), t1 = bf2f(qr.y), t2 = bf2f(qr.z), t3 = bf2f(qr.w);
    float4 q0 = make_float4(t0.x, t0.y, t1.x, t1.y);
    float4 q1 = make_float4(t2.x, t2.y, t3.x, t3.y);

    float acc[8] = {0.f, 0.f, 0.f, 0.f, 0.f, 0.f, 0.f, 0.f};
    float den = 0.f;

    const uint4* kvp = reinterpret_cast<const uint4*>(g_kv);

    int e0 = g_indptr[n], e1 = g_indptr[n + 1];
    int e = e0;

    for (; e + 2 <= e1; e += 2) {
        int sA = g_col[e], sB = g_col[e + 1];
        uint4 krA = kvp[(size_t)sA * 64 + koff];
        uint4 krB = kvp[(size_t)sB * 64 + koff];
        uint4 vrA = kvp[(size_t)sA * 64 + 32 + koff];
        uint4 vrB = kvp[(size_t)sB * 64 + 32 + koff];

        float2 a0 = bf2f(krA.x), a1 = bf2f(krA.y), a2 = bf2f(krA.z), a3 = bf2f(krA.w);
        float2 c0 = bf2f(krB.x), c1 = bf2f(krB.y), c2 = bf2f(krB.z), c3 = bf2f(krB.w);
        float pA = q0.x * a0.x + q0.y * a0.y + q0.z * a1.x + q0.w * a1.y
                 + q1.x * a2.x + q1.y * a2.y + q1.z * a3.x + q1.w * a3.y;
        float pB = q0.x * c0.x + q0.y * c0.y + q0.z * c1.x + q0.w * c1.y
                 + q1.x * c2.x + q1.y * c2.y + q1.z * c3.x + q1.w * c3.y;
        pA += __shfl_xor_sync(0xffffffffu, pA, 1);
        pB += __shfl_xor_sync(0xffffffffu, pB, 1);
        pA += __shfl_xor_sync(0xffffffffu, pA, 2);
        pB += __shfl_xor_sync(0xffffffffu, pB, 2);
        pA += __shfl_xor_sync(0xffffffffu, pA, 4);
        pB += __shfl_xor_sync(0xffffffffu, pB, 4);
        float exA = __expf(pA * 0.125f);
        float exB = __expf(pB * 0.125f);

        float2 vA0 = bf2f(vrA.x), vA1 = bf2f(vrA.y), vA2 = bf2f(vrA.z), vA3 = bf2f(vrA.w);
        float2 vB0 = bf2f(vrB.x), vB1 = bf2f(vrB.y), vB2 = bf2f(vrB.z), vB3 = bf2f(vrB.w);
        acc[0] += exA * vA0.x + exB * vB0.x;
        acc[1] += exA * vA0.y + exB * vB0.y;
        acc[2] += exA * vA1.x + exB * vB1.x;
        acc[3] += exA * vA1.y + exB * vB1.y;
        acc[4] += exA * vA2.x + exB * vB2.x;
        acc[5] += exA * vA2.y + exB * vB2.y;
        acc[6] += exA * vA3.x + exB * vB3.x;
        acc[7] += exA * vA3.y + exB * vB3.y;
        den += exA + exB;
    }
    if (e < e1) {
        int s = g_col[e];
        uint4 kr = kvp[(size_t)s * 64 + koff];
        uint4 vr = kvp[(size_t)s * 64 + 32 + koff];
        float2 k0 = bf2f(kr.x), k1 = bf2f(kr.y), k2 = bf2f(kr.z), k3 = bf2f(kr.w);
        float p = q0.x * k0.x + q0.y * k0.y + q0.z * k1.x + q0.w * k1.y
                + q1.x * k2.x + q1.y * k2.y + q1.z * k3.x + q1.w * k3.y;
        p += __shfl_xor_sync(0xffffffffu, p, 1);
        p += __shfl_xor_sync(0xffffffffu, p, 2);
        p += __shfl_xor_sync(0xffffffffu, p, 4);
        float ex = __expf(p * 0.125f);
        float2 v0 = bf2f(vr.x), v1 = bf2f(vr.y), v2 = bf2f(vr.z), v3 = bf2f(vr.w);
        acc[0] += ex * v0.x; acc[1] += ex * v0.y;
        acc[2] += ex * v1.x; acc[3] += ex * v1.y;
        acc[4] += ex * v2.x; acc[5] += ex * v2.y;
        acc[6] += ex * v3.x; acc[7] += ex * v3.y;
        den += ex;
    }

    float inv = 1.0f / (den + 1e-16f);
#pragma unroll
    for (int j = 0; j < 8; j++) {
        float r = acc[j] * inv;
        r += __shfl_xor_sync(0xffffffffu, r, 8);
        r += __shfl_xor_sync(0xffffffffu, r, 16);
        acc[j] = r * 0.25f;
    }

    if (h == 0) {
        float* out = to_gh ? g_h : out_ext;
        size_t ob = (size_t)n * DD + m * 8;
        float4 s0 = *reinterpret_cast<const float4*>(g_skip + ob);
        float4 s1 = *reinterpret_cast<const float4*>(g_skip + ob + 4);
        float4 o0, o1;
        o0.x = acc[0] + s0.x; o0.y = acc[1] + s0.y;
        o0.z = acc[2] + s0.z; o0.w = acc[3] + s0.w;
        o1.x = acc[4] + s1.x; o1.y = acc[5] + s1.y;
        o1.z = acc[6] + s1.z; o1.w = acc[7] + s1.w;
        if (relu) {
            o0.x = fmaxf(o0.x, 0.f); o0.y = fmaxf(o0.y, 0.f);
            o0.z = fmaxf(o0.z, 0.f); o0.w = fmaxf(o0.w, 0.f);
            o1.x = fmaxf(o1.x, 0.f); o1.y = fmaxf(o1.y, 0.f);
            o1.z = fmaxf(o1.z, 0.f); o1.w = fmaxf(o1.w, 0.f);
        }
        *reinterpret_cast<float4*>(out + ob)     = o0;
        *reinterpret_cast<float4*>(out + ob + 4) = o1;
    }
}

extern "C" void kernel_launch(void* const* d_in, const int* in_sizes, int n_in,
                              void* d_out, int out_size) {
    const float* x   = (const float*)d_in[0];
    const int*   ei  = (const int*)d_in[1];
    const float* Wq1 = (const float*)d_in[2];
    const float* bq1 = (const float*)d_in[3];
    const float* Wk1 = (const float*)d_in[4];
    const float* bk1 = (const float*)d_in[5];
    const float* Wv1 = (const float*)d_in[6];
    const float* bv1 = (const float*)d_in[7];
    const float* Ws1 = (const float*)d_in[8];
    const float* bs1 = (const float*)d_in[9];
    const float* Wq2 = (const float*)d_in[10];
    const float* bq2 = (const float*)d_in[11];
    const float* Wk2 = (const float*)d_in[12];
    const float* bk2 = (const float*)d_in[13];
    const float* Wv2 = (const float*)d_in[14];
    const float* bv2 = (const float*)d_in[15];
    const float* Ws2 = (const float*)d_in[16];
    const float* bs2 = (const float*)d_in[17];
    float* out = (float*)d_out;

    static cudaStream_t s_side = nullptr;
    static cudaEvent_t ev_root = nullptr, ev_side = nullptr;
    if (!s_side) {
        cudaStreamCreateWithFlags(&s_side, cudaStreamNonBlocking);
        cudaEventCreateWithFlags(&ev_root, cudaEventDisableTiming);
        cudaEventCreateWithFlags(&ev_side, cudaEventDisableTiming);
        cudaFuncSetAttribute(tc_gemm, cudaFuncAttributeMaxDynamicSharedMemorySize, SM_TOT);
    }

    __nv_bfloat16* wb_dev = nullptr;
    cudaGetSymbolAddress((void**)&wb_dev, g_wb);
    __nv_bfloat16* wb2 = wb_dev + 13 * 8192;

    int scan_blocks = (NN + 255) / 256;
    int gemm_blocks = (NN + 127) / 128;
    int attn_blocks = (NN * 32 + 255) / 256;

    // ---- fork: prep_w1 + gemm1 (side stream) || prep_w2 + CSR (main stream) ----
    cudaEventRecord(ev_root, 0);
    cudaStreamWaitEvent(s_side, ev_root, 0);

    prep_w<<<13, 256, 0, s_side>>>(Wq1, Wk1, Wv1, Ws1, wb_dev);
    tc_gemm<<<gemm_blocks, 128, SM_TOT, s_side>>>(x, 0, bq1, bk1, bv1, bs1, wb_dev, NN);
    cudaEventRecord(ev_side, s_side);

    prep_w<<<13, 256>>>(Wq2, Wk2, Wv2, Ws2, wb2);   // hidden under gemm1; ordered before gemm2
    zero_cnt_kernel<<<(NN + 255) / 256, 256>>>();
    hist_kernel<<<(EE + 255) / 256, 256>>>(ei);
    scan_local<<<scan_blocks, 256>>>();
    scan_bsums<<<1, 512>>>(scan_blocks);
    scan_add<<<scan_blocks, 256>>>();
    scatter_kernel<<<(EE + 255) / 256, 256>>>(ei);

    cudaStreamWaitEvent(0, ev_side, 0);

    attn_kernel<<<attn_blocks, 256>>>(nullptr, /*to_gh=*/1, /*relu=*/1);
    tc_gemm<<<gemm_blocks, 128, SM_TOT>>>(nullptr, 1, bq2, bk2, bv2, bs2, wb2, NN);
    attn_kernel<<<attn_blocks, 256>>>(out, /*to_gh=*/0, /*relu=*/0);
}

// round 17
// speedup vs baseline: 1.2582x; 1.0238x over previous
#include <cuda_runtime.h>
#include <cuda_bf16.h>
#include <cuda_fp16.h>
#include <cstdint>

#define NN 100000
#define EE 800000
#define DD 64
#define HH 4
#define HC 256

// ---- scratch (static device globals: allocation-free) ----
__device__ __nv_bfloat16 g_qb[(size_t)NN * HC];        // bf16 Q  [N][256]
__device__ uint8_t       g_k8[(size_t)NN * HC];        // fp8 e4m3 K [N][256]
__device__ __nv_bfloat16 g_v[(size_t)NN * HC];         // bf16 V [N][256]
__device__ float g_skip[(size_t)NN * DD];
__device__ float g_h[(size_t)NN * DD];
__device__ int   g_cnt[NN];
__device__ int   g_indptr[NN + 1];
__device__ int   g_cursor[NN];
__device__ int   g_col[EE];
__device__ int   g_bsum[512];
__device__ int   g_boff[512];
// W in bf16 hi/lo, transposed: [layer][chunk 13][part 2][n 64][k 64]
__device__ __nv_bfloat16 g_wb[2 * 13 * 2 * 64 * 64];

__device__ __forceinline__ uint32_t smem_u32(const void* p) {
    uint32_t a;
    asm("{ .reg .u64 t; cvta.to.shared.u64 t, %1; cvt.u32.u64 %0, t; }" : "=r"(a) : "l"(p));
    return a;
}
__device__ __forceinline__ float2 bf2f(unsigned u) {
    __nv_bfloat162 t = *reinterpret_cast<__nv_bfloat162*>(&u);
    return __bfloat1622float2(t);
}
__device__ __forceinline__ uint16_t f2e4m3x2(float hi, float lo) {
    uint16_t r;
    asm("cvt.rn.satfinite.e4m3x2.f32 %0, %1, %2;" : "=h"(r) : "f"(hi), "f"(lo));
    return r;
}
__device__ __forceinline__ float2 e4m3_f2(uint32_t u) {
    uint32_t h;
    asm("cvt.rn.f16x2.e4m3x2 %0, %1;" : "=r"(h) : "h"((uint16_t)u));
    __half2 t = *reinterpret_cast<__half2*>(&h);
    return __half22float2(t);
}

#define LDMX4(d0, d1, d2, d3, a) \
    asm volatile("ldmatrix.sync.aligned.m8n8.x4.shared.b16 {%0,%1,%2,%3}, [%4];" \
                 : "=r"(d0), "=r"(d1), "=r"(d2), "=r"(d3) : "r"(a))

#define MMA16816(c, a, b0, b1) \
    asm volatile("mma.sync.aligned.m16n8k16.row.col.f32.bf16.bf16.f32 " \
                 "{%0,%1,%2,%3}, {%4,%5,%6,%7}, {%8,%9}, {%0,%1,%2,%3};" \
                 : "+f"((c)[0]), "+f"((c)[1]), "+f"((c)[2]), "+f"((c)[3]) \
                 : "r"((a)[0]), "r"((a)[1]), "r"((a)[2]), "r"((a)[3]), "r"(b0), "r"(b1))

// ================= CSR build (per call, deterministic input) =================
__global__ void zero_cnt_kernel() {
    int i = blockIdx.x * blockDim.x + threadIdx.x;
    if (i < NN) g_cnt[i] = 0;
}
__global__ void hist_kernel(const int* __restrict__ ei) {
    int e = blockIdx.x * blockDim.x + threadIdx.x;
    if (e < EE) atomicAdd(&g_cnt[ei[EE + e]], 1);
}

__global__ void __launch_bounds__(256) scan_local() {
    __shared__ int s_w[8];
    int tid = threadIdx.x, lane = tid & 31, wid = tid >> 5;
    int i = blockIdx.x * 256 + tid;
    int v = (i < NN) ? g_cnt[i] : 0;
    int x = v;
#pragma unroll
    for (int d = 1; d < 32; d <<= 1) {
        int t = __shfl_up_sync(0xffffffffu, x, d);
        if (lane >= d) x += t;
    }
    if (lane == 31) s_w[wid] = x;
    __syncthreads();
    if (wid == 0 && lane < 8) {
        int y = s_w[lane];
#pragma unroll
        for (int d = 1; d < 8; d <<= 1) {
            int t = __shfl_up_sync(0xffu, y, d);
            if (lane >= d) y += t;
        }
        s_w[lane] = y;
    }
    __syncthreads();
    int excl = (wid > 0 ? s_w[wid - 1] : 0) + x - v;
    if (i < NN) g_indptr[i] = excl;
    if (tid == 255) g_bsum[blockIdx.x] = s_w[7];
}

__global__ void __launch_bounds__(512) scan_bsums(int nblocks) {
    __shared__ int s_w[16];
    int tid = threadIdx.x, lane = tid & 31, wid = tid >> 5;
    int v = (tid < nblocks) ? g_bsum[tid] : 0;
    int x = v;
#pragma unroll
    for (int d = 1; d < 32; d <<= 1) {
        int t = __shfl_up_sync(0xffffffffu, x, d);
        if (lane >= d) x += t;
    }
    if (lane == 31) s_w[wid] = x;
    __syncthreads();
    if (wid == 0 && lane < 16) {
        int y = s_w[lane];
#pragma unroll
        for (int d = 1; d < 16; d <<= 1) {
            int t = __shfl_up_sync(0xffffu, y, d);
            if (lane >= d) y += t;
        }
        s_w[lane] = y;
    }
    __syncthreads();
    int excl = (wid > 0 ? s_w[wid - 1] : 0) + x - v;
    if (tid < nblocks) g_boff[tid] = excl;
}

__global__ void __launch_bounds__(256) scan_add() {
    int i = blockIdx.x * 256 + threadIdx.x;
    if (i < NN) {
        int val = g_indptr[i] + g_boff[blockIdx.x];
        g_indptr[i] = val;
        g_cursor[i] = val;
    }
    if (i == 0) g_indptr[NN] = EE;
}

__global__ void scatter_kernel(const int* __restrict__ ei) {
    int e = blockIdx.x * blockDim.x + threadIdx.x;
    if (e < EE) {
        int d = ei[EE + e];
        int pos = atomicAdd(&g_cursor[d], 1);
        g_col[pos] = ei[e];
    }
}

// ============ W prep (one layer): transpose + bf16 hi/lo split ============
__global__ void prep_w(const float* __restrict__ Wq, const float* __restrict__ Wk,
                       const float* __restrict__ Wv, const float* __restrict__ Ws,
                       __nv_bfloat16* __restrict__ dst) {
    int c = blockIdx.x;           // 0..12
    for (int i = threadIdx.x; i < 4096; i += 256) {
        int n = i >> 6, k = i & 63;
        float w;
        if (c < 4)       w = Wq[k * 256 + c * 64 + n];
        else if (c < 8)  w = Wk[k * 256 + (c - 4) * 64 + n];
        else if (c < 12) w = Wv[k * 256 + (c - 8) * 64 + n];
        else             w = Ws[k * 64 + n];
        __nv_bfloat16 hi = __float2bfloat16(w);
        float lo = w - __bfloat162float(hi);
        dst[c * 8192 + i]        = hi;
        dst[c * 8192 + 4096 + i] = __float2bfloat16(lo);
    }
}

// ============ mma.sync GEMM: 128 rows x 832 cols ============
// chunks 0-3 (q): pure bf16 single-term, stored bf16
// chunks 4-7 (k): pure bf16 single-term, stored fp8 e4m3
// chunks 8-11 (v): bf16x3 split (fp32-accurate), stored bf16  <- error budget lives here
// chunk 12 (skip): bf16x3 split, stored fp32
#define SM_BIAS 0
#define SM_AHI  3584
#define SM_ALO  22016
#define SM_BHI  40448
#define SM_BLO  49664
#define SM_STG  58880
#define SM_TOT  93696
#define LDA 72
#define LDB 72
#define STG 68
#define STGU 36

__global__ void __launch_bounds__(128) tc_gemm(
    const float* __restrict__ Xext, int useGh,
    const float* __restrict__ bq, const float* __restrict__ bk,
    const float* __restrict__ bv, const float* __restrict__ bs,
    const __nv_bfloat16* __restrict__ wb, int nrows)
{
    extern __shared__ char smem[];
    uint32_t sb = smem_u32(smem);
    const float* X = useGh ? g_h : Xext;
    int tid = threadIdx.x, w = tid >> 5, l = tid & 31;
    int row0 = blockIdx.x * 128;
    float* biasSm = reinterpret_cast<float*>(smem + SM_BIAS);
    float* stage  = reinterpret_cast<float*>(smem + SM_STG);
    uint32_t* stu = reinterpret_cast<uint32_t*>(smem + SM_STG);

    for (int i = tid; i < 832; i += 128) {
        int c = i >> 6, j = i & 63;
        float b;
        if (c < 4)       b = bq[i];
        else if (c < 8)  b = bk[i - 256];
        else if (c < 12) b = bv[i - 512];
        else             b = bs[j];
        biasSm[i] = b;
    }

#pragma unroll
    for (int j = 0; j < 16; j++) {
        int idx = tid + j * 128;
        int r = idx >> 4, c4 = idx & 15;
        int gr = row0 + r;
        float4 xv = make_float4(0.f, 0.f, 0.f, 0.f);
        if (gr < nrows)
            xv = *reinterpret_cast<const float4*>(X + (size_t)gr * 64 + c4 * 4);
        __nv_bfloat16 h0 = __float2bfloat16(xv.x);
        __nv_bfloat16 h1 = __float2bfloat16(xv.y);
        __nv_bfloat16 h2 = __float2bfloat16(xv.z);
        __nv_bfloat16 h3 = __float2bfloat16(xv.w);
        __nv_bfloat162 hh0; hh0.x = h0; hh0.y = h1;
        __nv_bfloat162 hh1; hh1.x = h2; hh1.y = h3;
        __nv_bfloat162 ll0 = __floats2bfloat162_rn(xv.x - __bfloat162float(h0),
                                                   xv.y - __bfloat162float(h1));
        __nv_bfloat162 ll1 = __floats2bfloat162_rn(xv.z - __bfloat162float(h2),
                                                   xv.w - __bfloat162float(h3));
        uint2 uh, ul;
        uh.x = *reinterpret_cast<unsigned*>(&hh0);
        uh.y = *reinterpret_cast<unsigned*>(&hh1);
        ul.x = *reinterpret_cast<unsigned*>(&ll0);
        ul.y = *reinterpret_cast<unsigned*>(&ll1);
        size_t boff = (size_t)(r * LDA + c4 * 4) * 2;
        *reinterpret_cast<uint2*>(smem + SM_AHI + boff) = uh;
        *reinterpret_cast<uint2*>(smem + SM_ALO + boff) = ul;
    }

    int arow = w * 32 + (l & 15);
    int acol = (l >> 4) * 8;
    int bn   = (l & 7) + ((l >> 4) << 3);
    int bk8  = (l & 8);

    uint4 pre[4];
#pragma unroll
    for (int j = 0; j < 4; j++)
        pre[j] = reinterpret_cast<const uint4*>(wb)[tid + j * 128];

    for (int c = 0; c < 13; c++) {
#pragma unroll
        for (int j = 0; j < 4; j++) {
            int i = tid + j * 128;
            int n = i >> 3, k8 = i & 7;
            char* p = smem + SM_BHI + n * (LDB * 2) + k8 * 16;
            *reinterpret_cast<uint2*>(p)     = make_uint2(pre[j].x, pre[j].y);
            *reinterpret_cast<uint2*>(p + 8) = make_uint2(pre[j].z, pre[j].w);
        }
        if (c >= 8) {   // v + skip chunks: stage B-lo for 3-term split
#pragma unroll
            for (int j = 0; j < 4; j++) {
                int i = tid + j * 128;
                uint4 v = reinterpret_cast<const uint4*>(wb + (size_t)c * 8192 + 4096)[i];
                int n = i >> 3, k8 = i & 7;
                char* p = smem + SM_BLO + n * (LDB * 2) + k8 * 16;
                *reinterpret_cast<uint2*>(p)     = make_uint2(v.x, v.y);
                *reinterpret_cast<uint2*>(p + 8) = make_uint2(v.z, v.w);
            }
        }
        __syncthreads();

        if (c + 1 < 13) {
#pragma unroll
            for (int j = 0; j < 4; j++)
                pre[j] = reinterpret_cast<const uint4*>(wb + (size_t)(c + 1) * 8192)[tid + j * 128];
        }

        float acc[2][8][4];
#pragma unroll
        for (int mt = 0; mt < 2; mt++)
#pragma unroll
            for (int nt = 0; nt < 8; nt++)
#pragma unroll
                for (int q = 0; q < 4; q++) acc[mt][nt][q] = 0.f;

        if (c < 8) {
            // ---- q,k: pure bf16 single-term ----
#pragma unroll
            for (int kt = 0; kt < 4; kt++) {
                uint32_t ah[2][4];
#pragma unroll
                for (int mt = 0; mt < 2; mt++) {
                    uint32_t off = (uint32_t)(((arow + mt * 16) * LDA + kt * 16 + acol) * 2);
                    LDMX4(ah[mt][0], ah[mt][1], ah[mt][2], ah[mt][3], sb + SM_AHI + off);
                }
                uint32_t bh[4][4];
#pragma unroll
                for (int np = 0; np < 4; np++) {
                    uint32_t off = (uint32_t)(((bn + np * 16) * LDB + kt * 16 + bk8) * 2);
                    LDMX4(bh[np][0], bh[np][1], bh[np][2], bh[np][3], sb + SM_BHI + off);
                }
#pragma unroll
                for (int mt = 0; mt < 2; mt++) {
#pragma unroll
                    for (int np = 0; np < 4; np++) {
                        MMA16816(acc[mt][np * 2],     ah[mt], bh[np][0], bh[np][1]);
                        MMA16816(acc[mt][np * 2 + 1], ah[mt], bh[np][2], bh[np][3]);
                    }
                }
            }
        } else {
            // ---- v + skip: full bf16x3 split (fp32-accurate) ----
#pragma unroll
            for (int kt = 0; kt < 4; kt++) {
                uint32_t ah[2][4], al[2][4];
#pragma unroll
                for (int mt = 0; mt < 2; mt++) {
                    uint32_t off = (uint32_t)(((arow + mt * 16) * LDA + kt * 16 + acol) * 2);
                    LDMX4(ah[mt][0], ah[mt][1], ah[mt][2], ah[mt][3], sb + SM_AHI + off);
                    LDMX4(al[mt][0], al[mt][1], al[mt][2], al[mt][3], sb + SM_ALO + off);
                }
                uint32_t bh[4][4], bl[4][4];
#pragma unroll
                for (int np = 0; np < 4; np++) {
                    uint32_t off = (uint32_t)(((bn + np * 16) * LDB + kt * 16 + bk8) * 2);
                    LDMX4(bh[np][0], bh[np][1], bh[np][2], bh[np][3], sb + SM_BHI + off);
                    LDMX4(bl[np][0], bl[np][1], bl[np][2], bl[np][3], sb + SM_BLO + off);
                }
#pragma unroll
                for (int mt = 0; mt < 2; mt++) {
#pragma unroll
                    for (int np = 0; np < 4; np++) {
                        MMA16816(acc[mt][np * 2],     ah[mt], bh[np][0], bh[np][1]);
                        MMA16816(acc[mt][np * 2],     ah[mt], bl[np][0], bl[np][1]);
                        MMA16816(acc[mt][np * 2],     al[mt], bh[np][0], bh[np][1]);
                        MMA16816(acc[mt][np * 2 + 1], ah[mt], bh[np][2], bh[np][3]);
                        MMA16816(acc[mt][np * 2 + 1], ah[mt], bl[np][2], bl[np][3]);
                        MMA16816(acc[mt][np * 2 + 1], al[mt], bh[np][2], bh[np][3]);
                    }
                }
            }
        }

        if (c < 12) {
            // ---- bf16 staging: bias + pack during stage ----
            int rs = w * 32 + (l >> 2);
            int csh = (l & 3);
#pragma unroll
            for (int mt = 0; mt < 2; mt++) {
#pragma unroll
                for (int nt = 0; nt < 8; nt++) {
                    int colu = nt * 4 + csh;
                    int colc = colu * 2;
                    float b0 = biasSm[c * 64 + colc];
                    float b1 = biasSm[c * 64 + colc + 1];
                    __nv_bfloat162 p0 = __floats2bfloat162_rn(acc[mt][nt][0] + b0,
                                                              acc[mt][nt][1] + b1);
                    __nv_bfloat162 p1 = __floats2bfloat162_rn(acc[mt][nt][2] + b0,
                                                              acc[mt][nt][3] + b1);
                    stu[(rs + mt * 16) * STGU + colu]     = *reinterpret_cast<unsigned*>(&p0);
                    stu[(rs + mt * 16 + 8) * STGU + colu] = *reinterpret_cast<unsigned*>(&p1);
                }
            }
            __syncthreads();
#pragma unroll
            for (int j = 0; j < 8; j++) {
                int idx = tid + j * 128;
                int r = idx >> 3, cu4 = idx & 7;
                int gr = row0 + r;
                if (gr >= nrows) continue;
                uint4 u = *reinterpret_cast<const uint4*>(&stu[r * STGU + cu4 * 4]);
                if (c < 4) {
                    *reinterpret_cast<uint4*>(g_qb + (size_t)gr * 256 + c * 64 + cu4 * 8) = u;
                } else if (c < 8) {
                    float2 f0 = bf2f(u.x), f1 = bf2f(u.y), f2 = bf2f(u.z), f3 = bf2f(u.w);
                    uint16_t a01 = f2e4m3x2(f0.y, f0.x);
                    uint16_t a23 = f2e4m3x2(f1.y, f1.x);
                    uint16_t a45 = f2e4m3x2(f2.y, f2.x);
                    uint16_t a67 = f2e4m3x2(f3.y, f3.x);
                    uint2 o;
                    o.x = (uint32_t)a01 | ((uint32_t)a23 << 16);
                    o.y = (uint32_t)a45 | ((uint32_t)a67 << 16);
                    *reinterpret_cast<uint2*>(g_k8 + (size_t)gr * 256 + (c - 4) * 64 + cu4 * 8) = o;
                } else {
                    *reinterpret_cast<uint4*>(g_v + (size_t)gr * 256 + (c - 8) * 64 + cu4 * 8) = u;
                }
            }
            __syncthreads();
        } else {
            int rs = w * 32 + (l >> 2);
            int cs = (l & 3) * 2;
#pragma unroll
            for (int mt = 0; mt < 2; mt++) {
#pragma unroll
                for (int nt = 0; nt < 8; nt++) {
                    int col = nt * 8 + cs;
                    *reinterpret_cast<float2*>(stage + (rs + mt * 16) * STG + col) =
                        make_float2(acc[mt][nt][0], acc[mt][nt][1]);
                    *reinterpret_cast<float2*>(stage + (rs + mt * 16 + 8) * STG + col) =
                        make_float2(acc[mt][nt][2], acc[mt][nt][3]);
                }
            }
            __syncthreads();
#pragma unroll
            for (int j = 0; j < 16; j++) {
                int idx = tid + j * 128;
                int r = idx >> 4, c4 = idx & 15;
                int gr = row0 + r;
                if (gr >= nrows) continue;
                float4 o = *reinterpret_cast<const float4*>(stage + r * STG + c4 * 4);
                const float4 bb = *reinterpret_cast<const float4*>(biasSm + 12 * 64 + c4 * 4);
                o.x += bb.x; o.y += bb.y; o.z += bb.z; o.w += bb.w;
                *reinterpret_cast<float4*>(g_skip + (size_t)gr * 64 + c4 * 4) = o;
            }
            __syncthreads();
        }
    }
}

// ====== fused attention + epilogue: one warp per destination node ======
__global__ void __launch_bounds__(256) attn_kernel(float* __restrict__ out_ext,
                                                   int to_gh, int relu) {
    int n = (blockIdx.x * blockDim.x + threadIdx.x) >> 5;
    if (n >= NN) return;
    int lane = threadIdx.x & 31;
    int h = lane >> 3, m = lane & 7;
    int koff = h * 8 + m;

    uint4 qr = reinterpret_cast<const uint4*>(g_qb)[(size_t)n * 32 + koff];
    float2 t0 = bf2f(qr.x), t1 = bf2f(qr.y), t2 = bf2f(qr.z), t3 = bf2f(qr.w);
    float4 q0 = make_float4(t0.x, t0.y, t1.x, t1.y);
    float4 q1 = make_float4(t2.x, t2.y, t3.x, t3.y);

    float acc[8] = {0.f, 0.f, 0.f, 0.f, 0.f, 0.f, 0.f, 0.f};
    float den = 0.f;

    const uint2* k8p = reinterpret_cast<const uint2*>(g_k8);  // node stride 32 uint2
    const uint4* vp  = reinterpret_cast<const uint4*>(g_v);   // node stride 32 uint4

    int e0 = g_indptr[n], e1 = g_indptr[n + 1];
    int e = e0;

    for (; e + 2 <= e1; e += 2) {
        int sA = g_col[e], sB = g_col[e + 1];
        uint2 krA = k8p[(size_t)sA * 32 + koff];
        uint2 krB = k8p[(size_t)sB * 32 + koff];
        uint4 vrA = vp[(size_t)sA * 32 + koff];
        uint4 vrB = vp[(size_t)sB * 32 + koff];

        float2 a0 = e4m3_f2(krA.x & 0xffffu), a1 = e4m3_f2(krA.x >> 16);
        float2 a2 = e4m3_f2(krA.y & 0xffffu), a3 = e4m3_f2(krA.y >> 16);
        float2 c0 = e4m3_f2(krB.x & 0xffffu), c1 = e4m3_f2(krB.x >> 16);
        float2 c2 = e4m3_f2(krB.y & 0xffffu), c3 = e4m3_f2(krB.y >> 16);
        float pA = q0.x * a0.x + q0.y * a0.y + q0.z * a1.x + q0.w * a1.y
                 + q1.x * a2.x + q1.y * a2.y + q1.z * a3.x + q1.w * a3.y;
        float pB = q0.x * c0.x + q0.y * c0.y + q0.z * c1.x + q0.w * c1.y
                 + q1.x * c2.x + q1.y * c2.y + q1.z * c3.x + q1.w * c3.y;
        pA += __shfl_xor_sync(0xffffffffu, pA, 1);
        pB += __shfl_xor_sync(0xffffffffu, pB, 1);
        pA += __shfl_xor_sync(0xffffffffu, pA, 2);
        pB += __shfl_xor_sync(0xffffffffu, pB, 2);
        pA += __shfl_xor_sync(0xffffffffu, pA, 4);
        pB += __shfl_xor_sync(0xffffffffu, pB, 4);
        float exA = __expf(pA * 0.125f);
        float exB = __expf(pB * 0.125f);

        float2 vA0 = bf2f(vrA.x), vA1 = bf2f(vrA.y), vA2 = bf2f(vrA.z), vA3 = bf2f(vrA.w);
        float2 vB0 = bf2f(vrB.x), vB1 = bf2f(vrB.y), vB2 = bf2f(vrB.z), vB3 = bf2f(vrB.w);
        acc[0] += exA * vA0.x + exB * vB0.x;
        acc[1] += exA * vA0.y + exB * vB0.y;
        acc[2] += exA * vA1.x + exB * vB1.x;
        acc[3] += exA * vA1.y + exB * vB1.y;
        acc[4] += exA * vA2.x + exB * vB2.x;
        acc[5] += exA * vA2.y + exB * vB2.y;
        acc[6] += exA * vA3.x + exB * vB3.x;
        acc[7] += exA * vA3.y + exB * vB3.y;
        den += exA + exB;
    }
    if (e < e1) {
        int s = g_col[e];
        uint2 kr = k8p[(size_t)s * 32 + koff];
        uint4 vr = vp[(size_t)s * 32 + koff];
        float2 k0 = e4m3_f2(kr.x & 0xffffu), k1 = e4m3_f2(kr.x >> 16);
        float2 k2 = e4m3_f2(kr.y & 0xffffu), k3 = e4m3_f2(kr.y >> 16);
        float p = q0.x * k0.x + q0.y * k0.y + q0.z * k1.x + q0.w * k1.y
                + q1.x * k2.x + q1.y * k2.y + q1.z * k3.x + q1.w * k3.y;
        p += __shfl_xor_sync(0xffffffffu, p, 1);
        p += __shfl_xor_sync(0xffffffffu, p, 2);
        p += __shfl_xor_sync(0xffffffffu, p, 4);
        float ex = __expf(p * 0.125f);
        float2 v0 = bf2f(vr.x), v1 = bf2f(vr.y), v2 = bf2f(vr.z), v3 = bf2f(vr.w);
        acc[0] += ex * v0.x; acc[1] += ex * v0.y;
        acc[2] += ex * v1.x; acc[3] += ex * v1.y;
        acc[4] += ex * v2.x; acc[5] += ex * v2.y;
        acc[6] += ex * v3.x; acc[7] += ex * v3.y;
        den += ex;
    }

    float inv = 1.0f / (den + 1e-16f);
#pragma unroll
    for (int j = 0; j < 8; j++) {
        float r = acc[j] * inv;
        r += __shfl_xor_sync(0xffffffffu, r, 8);
        r += __shfl_xor_sync(0xffffffffu, r, 16);
        acc[j] = r * 0.25f;
    }

    if (h == 0) {
        float* out = to_gh ? g_h : out_ext;
        size_t ob = (size_t)n * DD + m * 8;
        float4 s0 = *reinterpret_cast<const float4*>(g_skip + ob);
        float4 s1 = *reinterpret_cast<const float4*>(g_skip + ob + 4);
        float4 o0, o1;
        o0.x = acc[0] + s0.x; o0.y = acc[1] + s0.y;
        o0.z = acc[2] + s0.z; o0.w = acc[3] + s0.w;
        o1.x = acc[4] + s1.x; o1.y = acc[5] + s1.y;
        o1.z = acc[6] + s1.z; o1.w = acc[7] + s1.w;
        if (relu) {
            o0.x = fmaxf(o0.x, 0.f); o0.y = fmaxf(o0.y, 0.f);
            o0.z = fmaxf(o0.z, 0.f); o0.w = fmaxf(o0.w, 0.f);
            o1.x = fmaxf(o1.x, 0.f); o1.y = fmaxf(o1.y, 0.f);
            o1.w = fmaxf(o1.w, 0.f); o1.z = fmaxf(o1.z, 0.f);
        }
        *reinterpret_cast<float4*>(out + ob)     = o0;
        *reinterpret_cast<float4*>(out + ob + 4) = o1;
    }
}

extern "C" void kernel_launch(void* const* d_in, const int* in_sizes, int n_in,
                              void* d_out, int out_size) {
    const float* x   = (const float*)d_in[0];
    const int*   ei  = (const int*)d_in[1];
    const float* Wq1 = (const float*)d_in[2];
    const float* bq1 = (const float*)d_in[3];
    const float* Wk1 = (const float*)d_in[4];
    const float* bk1 = (const float*)d_in[5];
    const float* Wv1 = (const float*)d_in[6];
    const float* bv1 = (const float*)d_in[7];
    const float* Ws1 = (const float*)d_in[8];
    const float* bs1 = (const float*)d_in[9];
    const float* Wq2 = (const float*)d_in[10];
    const float* bq2 = (const float*)d_in[11];
    const float* Wk2 = (const float*)d_in[12];
    const float* bk2 = (const float*)d_in[13];
    const float* Wv2 = (const float*)d_in[14];
    const float* bv2 = (const float*)d_in[15];
    const float* Ws2 = (const float*)d_in[16];
    const float* bs2 = (const float*)d_in[17];
    float* out = (float*)d_out;

    static cudaStream_t s_side = nullptr;
    static cudaEvent_t ev_root = nullptr, ev_side = nullptr;
    if (!s_side) {
        cudaStreamCreateWithFlags(&s_side, cudaStreamNonBlocking);
        cudaEventCreateWithFlags(&ev_root, cudaEventDisableTiming);
        cudaEventCreateWithFlags(&ev_side, cudaEventDisableTiming);
        cudaFuncSetAttribute(tc_gemm, cudaFuncAttributeMaxDynamicSharedMemorySize, SM_TOT);
    }

    __nv_bfloat16* wb_dev = nullptr;
    cudaGetSymbolAddress((void**)&wb_dev, g_wb);
    __nv_bfloat16* wb2 = wb_dev + 13 * 8192;

    int scan_blocks = (NN + 255) / 256;
    int gemm_blocks = (NN + 127) / 128;
    int attn_blocks = (NN * 32 + 255) / 256;

    // ---- fork: prep_w1 + gemm1 (side stream) || prep_w2 + CSR (main stream) ----
    cudaEventRecord(ev_root, 0);
    cudaStreamWaitEvent(s_side, ev_root, 0);

    prep_w<<<13, 256, 0, s_side>>>(Wq1, Wk1, Wv1, Ws1, wb_dev);
    tc_gemm<<<gemm_blocks, 128, SM_TOT, s_side>>>(x, 0, bq1, bk1, bv1, bs1, wb_dev, NN);
    cudaEventRecord(ev_side, s_side);

    prep_w<<<13, 256>>>(Wq2, Wk2, Wv2, Ws2, wb2);
    zero_cnt_kernel<<<(NN + 255) / 256, 256>>>();
    hist_kernel<<<(EE + 255) / 256, 256>>>(ei);
    scan_local<<<scan_blocks, 256>>>();
    scan_bsums<<<1, 512>>>(scan_blocks);
    scan_add<<<scan_blocks, 256>>>();
    scatter_kernel<<<(EE + 255) / 256, 256>>>(ei);

    cudaStreamWaitEvent(0, ev_side, 0);

    attn_kernel<<<attn_blocks, 256>>>(nullptr, /*to_gh=*/1, /*relu=*/1);
    tc_gemm<<<gemm_blocks, 128, SM_TOT>>>(nullptr, 1, bq2, bk2, bv2, bs2, wb2, NN);
    attn_kernel<<<attn_blocks, 256>>>(out, /*to_gh=*/0, /*relu=*/0);
}